// round 1
// baseline (speedup 1.0000x reference)
#include <cuda_runtime.h>

#define MTOT 16384   // B*T*N = 2*8*1024
#define DDIM 512
#define NSEQ 1024
#define NHEAD 8
#define DH 64

// Scratch (device globals; no allocation allowed)
__device__ float g_Q[MTOT * DDIM];
__device__ float g_K[MTOT * DDIM];
__device__ float g_V[MTOT * DDIM];
__device__ float g_Z[MTOT * DDIM];

// C[m,e] = sum_k A[m,k] * W[e,k] + bias[e]
// Tiles: 128(m) x 128(e), K-step 8. 256 threads, each computes 8x8.
// mode: 0 -> C=g_Q, 1 -> C=g_K, 2 -> C=g_V, 3 -> A=g_Z, C=out_ext
__global__ __launch_bounds__(256, 2) void gemm_kernel(
    int mode,
    const float* __restrict__ Ain,
    const float* __restrict__ W,
    const float* __restrict__ bias,
    float* __restrict__ out_ext)
{
    const float* A = (mode == 3) ? g_Z : Ain;
    float* C;
    if (mode == 0)      C = g_Q;
    else if (mode == 1) C = g_K;
    else if (mode == 2) C = g_V;
    else                C = out_ext;

    __shared__ __align__(16) float As[8][128];
    __shared__ __align__(16) float Ws[8][128];

    int tid = threadIdx.x;
    int tx = tid & 15;      // 0..15  (e direction, stride 16)
    int ty = tid >> 4;      // 0..15  (m direction, stride 16)
    int bm = blockIdx.y * 128;
    int be = blockIdx.x * 128;

    float acc[8][8];
#pragma unroll
    for (int i = 0; i < 8; i++)
#pragma unroll
        for (int j = 0; j < 8; j++) acc[i][j] = 0.f;

    // loader mapping: each thread loads one float4 of A-tile and one of W-tile
    int lr = tid >> 1;           // 0..127 row within tile
    int lc = (tid & 1) * 4;      // 0 or 4 within 8-wide K slice
    const float* Ap = A + (size_t)(bm + lr) * DDIM + lc;
    const float* Wp = W + (size_t)(be + lr) * DDIM + lc;

    for (int k0 = 0; k0 < DDIM; k0 += 8) {
        float4 av = *(const float4*)(Ap + k0);
        float4 wv = *(const float4*)(Wp + k0);
        __syncthreads();
        As[lc + 0][lr] = av.x; As[lc + 1][lr] = av.y;
        As[lc + 2][lr] = av.z; As[lc + 3][lr] = av.w;
        Ws[lc + 0][lr] = wv.x; Ws[lc + 1][lr] = wv.y;
        Ws[lc + 2][lr] = wv.z; Ws[lc + 3][lr] = wv.w;
        __syncthreads();
#pragma unroll
        for (int kk = 0; kk < 8; kk++) {
            float a[8], w[8];
#pragma unroll
            for (int i = 0; i < 8; i++) a[i] = As[kk][ty + i * 16];
#pragma unroll
            for (int j = 0; j < 8; j++) w[j] = Ws[kk][tx + j * 16];
#pragma unroll
            for (int i = 0; i < 8; i++)
#pragma unroll
                for (int j = 0; j < 8; j++)
                    acc[i][j] = fmaf(a[i], w[j], acc[i][j]);
        }
    }

#pragma unroll
    for (int j = 0; j < 8; j++) {
        float b = bias[be + tx + j * 16];
#pragma unroll
        for (int i = 0; i < 8; i++) {
            C[(size_t)(bm + ty + i * 16) * DDIM + be + tx + j * 16] = acc[i][j] + b;
        }
    }
}

// Flash attention, fp32. One query row per thread, 128 rows per CTA.
// Grid: (NSEQ/128, NHEAD, B*T). The delta_c bias is constant along the softmax
// axis and therefore cancels — omitted.
__global__ __launch_bounds__(128) void attn_kernel()
{
    __shared__ __align__(16) float Ks[32][DH];
    __shared__ __align__(16) float Vs[32][DH];

    int bt = blockIdx.z;
    int h  = blockIdx.y;
    int row = blockIdx.x * 128 + threadIdx.x;
    size_t base = (size_t)bt * NSEQ * DDIM + h * DH;

    // load + pre-scale q
    const float* Qp = g_Q + base + (size_t)row * DDIM;
    float q[DH];
    const float sc = 0.125f;   // 1/sqrt(64)
#pragma unroll
    for (int k = 0; k < DH; k += 4) {
        float4 v = *(const float4*)(Qp + k);
        q[k] = v.x * sc; q[k + 1] = v.y * sc; q[k + 2] = v.z * sc; q[k + 3] = v.w * sc;
    }

    float mx = -1e30f, l = 0.f;
    float z[DH];
#pragma unroll
    for (int k = 0; k < DH; k++) z[k] = 0.f;

    for (int j0 = 0; j0 < NSEQ; j0 += 32) {
        __syncthreads();
        // stage 32x64 K and V tiles: 512 float4 each, 4 per thread
        for (int t = threadIdx.x; t < 512; t += 128) {
            int r = t >> 4;
            int c = (t & 15) * 4;
            *(float4*)&Ks[r][c] = *(const float4*)(g_K + base + (size_t)(j0 + r) * DDIM + c);
            *(float4*)&Vs[r][c] = *(const float4*)(g_V + base + (size_t)(j0 + r) * DDIM + c);
        }
        __syncthreads();

        float s[32];
#pragma unroll
        for (int j = 0; j < 32; j++) {
            float acc = 0.f;
#pragma unroll
            for (int k = 0; k < DH; k += 4) {
                float4 kv = *(const float4*)&Ks[j][k];
                acc = fmaf(q[k], kv.x,
                      fmaf(q[k + 1], kv.y,
                      fmaf(q[k + 2], kv.z,
                      fmaf(q[k + 3], kv.w, acc))));
            }
            s[j] = acc;
        }

        float mt = mx;
#pragma unroll
        for (int j = 0; j < 32; j++) mt = fmaxf(mt, s[j]);
        float corr = __expf(mx - mt);
        mx = mt;

        float ps = 0.f;
#pragma unroll
        for (int j = 0; j < 32; j++) { s[j] = __expf(s[j] - mt); ps += s[j]; }
        l = l * corr + ps;

#pragma unroll
        for (int k = 0; k < DH; k++) z[k] *= corr;

#pragma unroll
        for (int j = 0; j < 32; j++) {
            float p = s[j];
#pragma unroll
            for (int k = 0; k < DH; k += 4) {
                float4 vv = *(const float4*)&Vs[j][k];
                z[k]     = fmaf(p, vv.x, z[k]);
                z[k + 1] = fmaf(p, vv.y, z[k + 1]);
                z[k + 2] = fmaf(p, vv.z, z[k + 2]);
                z[k + 3] = fmaf(p, vv.w, z[k + 3]);
            }
        }
    }

    float inv = 1.f / l;
    float* Zp = g_Z + base + (size_t)row * DDIM;
#pragma unroll
    for (int k = 0; k < DH; k += 4) {
        float4 v;
        v.x = z[k] * inv; v.y = z[k + 1] * inv;
        v.z = z[k + 2] * inv; v.w = z[k + 3] * inv;
        *(float4*)(Zp + k) = v;
    }
}

extern "C" void kernel_launch(void* const* d_in, const int* in_sizes, int n_in,
                              void* d_out, int out_size)
{
    const float* X  = (const float*)d_in[0];
    const float* Wq = (const float*)d_in[1];
    const float* bq = (const float*)d_in[2];
    const float* Wk = (const float*)d_in[3];
    const float* bk = (const float*)d_in[4];
    const float* Wv = (const float*)d_in[5];
    const float* bv = (const float*)d_in[6];
    const float* Wo = (const float*)d_in[7];
    const float* bo = (const float*)d_in[8];
    float* out = (float*)d_out;

    dim3 gg(DDIM / 128, MTOT / 128);   // (4, 128)
    gemm_kernel<<<gg, 256>>>(0, X, Wq, bq, nullptr);
    gemm_kernel<<<gg, 256>>>(1, X, Wk, bk, nullptr);
    gemm_kernel<<<gg, 256>>>(2, X, Wv, bv, nullptr);

    dim3 ga(NSEQ / 128, NHEAD, 16);    // (8, 8, 16)
    attn_kernel<<<ga, 128>>>();

    gemm_kernel<<<gg, 256>>>(3, nullptr, Wo, bo, out);
}

// round 3
// speedup vs baseline: 1.1667x; 1.1667x over previous
#include <cuda_runtime.h>

#define MTOT 16384   // B*T*N
#define DDIM 512
#define NSEQ 1024
#define NHEAD 8
#define DH 64

typedef unsigned long long u64;

__device__ float g_Q[MTOT * DDIM];
__device__ float g_K[MTOT * DDIM];
__device__ float g_V[MTOT * DDIM];
__device__ float g_Z[MTOT * DDIM];

__device__ __forceinline__ u64 pack2(float lo, float hi) {
    u64 r;
    asm("mov.b64 %0, {%1, %2};" : "=l"(r) : "f"(lo), "f"(hi));
    return r;
}
__device__ __forceinline__ void unpack2(u64 v, float& lo, float& hi) {
    asm("mov.b64 {%0, %1}, %2;" : "=f"(lo), "=f"(hi) : "l"(v));
}
__device__ __forceinline__ u64 fma2(u64 a, u64 b, u64 c) {
    u64 d;
    asm("fma.rn.f32x2 %0, %1, %2, %3;" : "=l"(d) : "l"(a), "l"(b), "l"(c));
    return d;
}
__device__ __forceinline__ u64 mul2(u64 a, u64 b) {
    u64 d;
    asm("mul.rn.f32x2 %0, %1, %2;" : "=l"(d) : "l"(a), "l"(b));
    return d;
}
__device__ __forceinline__ u64 add2(u64 a, u64 b) {
    u64 d;
    asm("add.rn.f32x2 %0, %1, %2;" : "=l"(d) : "l"(a), "l"(b));
    return d;
}

// C[m,e] = sum_k A[m,k] * W[e,k] + bias[e]
// 128x128 tile, 256 threads, 8 (m) x 4x2 (e) per thread, packed f32x2 FMAs.
// Thread (tx,ty): rows bm+ty+i*16, cols be + tx*2 + jp*32 (+0/+1)
__device__ __forceinline__ void gemm_body(
    const float* __restrict__ A,
    const float* __restrict__ W,
    const float* __restrict__ bias,
    float* __restrict__ C,
    int bm, int be)
{
    __shared__ __align__(16) float As[8][128];
    __shared__ __align__(16) float Ws[8][128];

    int tid = threadIdx.x;
    int tx = tid & 15;
    int ty = tid >> 4;

    u64 acc[8][4];
#pragma unroll
    for (int i = 0; i < 8; i++)
#pragma unroll
        for (int j = 0; j < 4; j++) acc[i][j] = 0ull;

    int lr = tid >> 1;
    int lc = (tid & 1) * 4;
    const float* Ap = A + (size_t)(bm + lr) * DDIM + lc;
    const float* Wp = W + (size_t)(be + lr) * DDIM + lc;

    for (int k0 = 0; k0 < DDIM; k0 += 8) {
        float4 av = *(const float4*)(Ap + k0);
        float4 wv = *(const float4*)(Wp + k0);
        __syncthreads();
        As[lc + 0][lr] = av.x; As[lc + 1][lr] = av.y;
        As[lc + 2][lr] = av.z; As[lc + 3][lr] = av.w;
        Ws[lc + 0][lr] = wv.x; Ws[lc + 1][lr] = wv.y;
        Ws[lc + 2][lr] = wv.z; Ws[lc + 3][lr] = wv.w;
        __syncthreads();
#pragma unroll
        for (int kk = 0; kk < 8; kk++) {
            u64 w2[4];
#pragma unroll
            for (int j = 0; j < 4; j++)
                w2[j] = *(const u64*)&Ws[kk][tx * 2 + j * 32];
            u64 a2[8];
#pragma unroll
            for (int i = 0; i < 8; i++) {
                float a = As[kk][ty + i * 16];
                a2[i] = pack2(a, a);
            }
#pragma unroll
            for (int i = 0; i < 8; i++)
#pragma unroll
                for (int j = 0; j < 4; j++)
                    acc[i][j] = fma2(a2[i], w2[j], acc[i][j]);
        }
    }

#pragma unroll
    for (int j = 0; j < 4; j++) {
        int col = be + tx * 2 + j * 32;
        u64 b2 = pack2(bias[col], bias[col + 1]);
#pragma unroll
        for (int i = 0; i < 8; i++) {
            u64 r = add2(acc[i][j], b2);
            *(u64*)&C[(size_t)(bm + ty + i * 16) * DDIM + col] = r;
        }
    }
}

// Fused QKV: blockIdx.z selects which projection
__global__ __launch_bounds__(256, 2) void qkv_kernel(
    const float* __restrict__ X,
    const float* __restrict__ Wq, const float* __restrict__ bq,
    const float* __restrict__ Wk, const float* __restrict__ bk,
    const float* __restrict__ Wv, const float* __restrict__ bv)
{
    int z = blockIdx.z;
    const float* W = (z == 0) ? Wq : (z == 1) ? Wk : Wv;
    const float* b = (z == 0) ? bq : (z == 1) ? bk : bv;
    float* C = (z == 0) ? g_Q : (z == 1) ? g_K : g_V;
    gemm_body(X, W, b, C, blockIdx.y * 128, blockIdx.x * 128);
}

__global__ __launch_bounds__(256, 2) void out_kernel(
    const float* __restrict__ Wo, const float* __restrict__ bo,
    float* __restrict__ out)
{
    gemm_body(g_Z, Wo, bo, out, blockIdx.y * 128, blockIdx.x * 128);
}

// Flash attention, packed f32x2. One query row per thread, 128 rows per CTA.
// delta_c bias is constant along the softmax axis -> cancels, omitted.
__global__ __launch_bounds__(128) void attn_kernel()
{
    __shared__ __align__(16) float Ks[32][DH];
    __shared__ __align__(16) float Vs[32][DH];

    int bt = blockIdx.z;
    int h  = blockIdx.y;
    int row = blockIdx.x * 128 + threadIdx.x;
    size_t base = (size_t)bt * NSEQ * DDIM + h * DH;

    const float* Qp = g_Q + base + (size_t)row * DDIM;
    const float sc = 0.125f;   // 1/sqrt(64)
    u64 q2[32];
#pragma unroll
    for (int k = 0; k < DH; k += 4) {
        float4 v = *(const float4*)(Qp + k);
        q2[k / 2]     = pack2(v.x * sc, v.y * sc);
        q2[k / 2 + 1] = pack2(v.z * sc, v.w * sc);
    }

    float mx = -1e30f, l = 0.f;
    u64 z2[32];
#pragma unroll
    for (int k = 0; k < 32; k++) z2[k] = 0ull;

    for (int j0 = 0; j0 < NSEQ; j0 += 32) {
        __syncthreads();
        for (int t = threadIdx.x; t < 512; t += 128) {
            int r = t >> 4;
            int c = (t & 15) * 4;
            *(float4*)&Ks[r][c] = *(const float4*)(g_K + base + (size_t)(j0 + r) * DDIM + c);
            *(float4*)&Vs[r][c] = *(const float4*)(g_V + base + (size_t)(j0 + r) * DDIM + c);
        }
        __syncthreads();

        float s[32];
#pragma unroll
        for (int j = 0; j < 32; j++) {
            const u64* kp = (const u64*)&Ks[j][0];
            u64 accA = 0ull, accB = 0ull;
#pragma unroll
            for (int k = 0; k < 32; k += 2) {
                accA = fma2(q2[k],     kp[k],     accA);
                accB = fma2(q2[k + 1], kp[k + 1], accB);
            }
            u64 acc = add2(accA, accB);
            float lo, hi;
            unpack2(acc, lo, hi);
            s[j] = lo + hi;
        }

        float mt = mx;
#pragma unroll
        for (int j = 0; j < 32; j++) mt = fmaxf(mt, s[j]);
        float corr = __expf(mx - mt);
        mx = mt;

        float ps = 0.f;
#pragma unroll
        for (int j = 0; j < 32; j++) { s[j] = __expf(s[j] - mt); ps += s[j]; }
        l = l * corr + ps;

        u64 corr2 = pack2(corr, corr);
#pragma unroll
        for (int k = 0; k < 32; k++) z2[k] = mul2(z2[k], corr2);

#pragma unroll
        for (int j = 0; j < 32; j++) {
            u64 p2 = pack2(s[j], s[j]);
            const u64* vp = (const u64*)&Vs[j][0];
#pragma unroll
            for (int k = 0; k < 32; k++)
                z2[k] = fma2(p2, vp[k], z2[k]);
        }
    }

    float inv = 1.f / l;
    u64 inv2 = pack2(inv, inv);
    float* Zp = g_Z + base + (size_t)row * DDIM;
#pragma unroll
    for (int k = 0; k < 32; k++)
        *(u64*)&Zp[k * 2] = mul2(z2[k], inv2);
}

extern "C" void kernel_launch(void* const* d_in, const int* in_sizes, int n_in,
                              void* d_out, int out_size)
{
    const float* X  = (const float*)d_in[0];
    const float* Wq = (const float*)d_in[1];
    const float* bq = (const float*)d_in[2];
    const float* Wk = (const float*)d_in[3];
    const float* bk = (const float*)d_in[4];
    const float* Wv = (const float*)d_in[5];
    const float* bv = (const float*)d_in[6];
    const float* Wo = (const float*)d_in[7];
    const float* bo = (const float*)d_in[8];
    float* out = (float*)d_out;

    dim3 gq(DDIM / 128, MTOT / 128, 3);   // (4, 128, 3)
    qkv_kernel<<<gq, 256>>>(X, Wq, bq, Wk, bk, Wv, bv);

    dim3 ga(NSEQ / 128, NHEAD, 16);       // (8, 8, 16)
    attn_kernel<<<ga, 128>>>();

    dim3 go(DDIM / 128, MTOT / 128);      // (4, 128)
    out_kernel<<<go, 256>>>(Wo, bo, out);
}

// round 5
// speedup vs baseline: 2.1074x; 1.8063x over previous
#include <cuda_runtime.h>
#include <cuda_bf16.h>
#include <stdint.h>

typedef uint32_t u32;
typedef unsigned short u16;

#define MTOT 16384   // B*T*N
#define DDIM 512
#define NSEQ 1024
#define DH 64
#define NINST 128    // (B*T)*HEADS

// ---------------- scratch (device globals; no allocation allowed) ----------
__device__ __nv_bfloat16 g_Xh[MTOT*DDIM], g_Xl[MTOT*DDIM];
__device__ __nv_bfloat16 g_Wh[4*DDIM*DDIM], g_Wl[4*DDIM*DDIM];
__device__ __nv_bfloat16 g_Qh[MTOT*DDIM], g_Ql[MTOT*DDIM];
__device__ __nv_bfloat16 g_Kh[MTOT*DDIM], g_Kl[MTOT*DDIM];
__device__ __nv_bfloat16 g_Vth[MTOT*DDIM], g_Vtl[MTOT*DDIM];  // V transposed [d, n]
__device__ __nv_bfloat16 g_Zh[MTOT*DDIM], g_Zl[MTOT*DDIM];
__device__ float         g_S [(size_t)NINST*NSEQ*NSEQ];
__device__ __nv_bfloat16 g_Ph[(size_t)NINST*NSEQ*NSEQ];
__device__ __nv_bfloat16 g_Pl[(size_t)NINST*NSEQ*NSEQ];

// ---------------- helpers ---------------------------------------------------
__device__ __forceinline__ void mma_bf16(float* c, const u32* a, const u32* b) {
    asm volatile(
        "mma.sync.aligned.m16n8k16.row.col.f32.bf16.bf16.f32 "
        "{%0,%1,%2,%3}, {%4,%5,%6,%7}, {%8,%9}, {%0,%1,%2,%3};"
        : "+f"(c[0]), "+f"(c[1]), "+f"(c[2]), "+f"(c[3])
        : "r"(a[0]), "r"(a[1]), "r"(a[2]), "r"(a[3]), "r"(b[0]), "r"(b[1]));
}

__device__ __forceinline__ u32 split_pack(float v) {
    __nv_bfloat16 h = __float2bfloat16(v);
    float r = v - __bfloat162float(h);
    __nv_bfloat16 l = __float2bfloat16(r);
    return (u32)__bfloat16_as_ushort(h) | ((u32)__bfloat16_as_ushort(l) << 16);
}
__device__ __forceinline__ __nv_bfloat16 lo_bf(u32 u) { return __ushort_as_bfloat16((u16)(u & 0xFFFF)); }
__device__ __forceinline__ __nv_bfloat16 hi_bf(u32 u) { return __ushort_as_bfloat16((u16)(u >> 16)); }

// load ROWS x 32 bf16 tile into smem (stride 40 elems), 256 threads
template<int ROWS>
__device__ __forceinline__ void ld_tile(__nv_bfloat16* dst, const __nv_bfloat16* src, int ld) {
    int t = threadIdx.x;
#pragma unroll
    for (int i = t; i < ROWS * 2; i += 256) {
        int r = i >> 1, c = (i & 1) * 16;
        const uint4* s = (const uint4*)(src + (size_t)r * ld + c);
        uint4* d = (uint4*)(dst + r * 40 + c);
        d[0] = s[0]; d[1] = s[1];
    }
}

// one K=32 chunk of 3-pass bf16 mma. Warp tile 64 x (8*NF).
template<int NF>
__device__ __forceinline__ void mma_chunk(
    const __nv_bfloat16* Ah, const __nv_bfloat16* Al,
    const __nv_bfloat16* Bh, const __nv_bfloat16* Bl,
    int wm, int wn, int g, int tg, float acc[4][NF][4])
{
#pragma unroll
    for (int s = 0; s < 2; s++) {
        int kc = s * 16 + tg * 2;
        u32 ah[4][4], al[4][4];
#pragma unroll
        for (int mf = 0; mf < 4; mf++) {
            int r0 = wm + mf * 16 + g;
            ah[mf][0] = *(const u32*)&Ah[r0 * 40 + kc];
            ah[mf][1] = *(const u32*)&Ah[(r0 + 8) * 40 + kc];
            ah[mf][2] = *(const u32*)&Ah[r0 * 40 + kc + 8];
            ah[mf][3] = *(const u32*)&Ah[(r0 + 8) * 40 + kc + 8];
            al[mf][0] = *(const u32*)&Al[r0 * 40 + kc];
            al[mf][1] = *(const u32*)&Al[(r0 + 8) * 40 + kc];
            al[mf][2] = *(const u32*)&Al[r0 * 40 + kc + 8];
            al[mf][3] = *(const u32*)&Al[(r0 + 8) * 40 + kc + 8];
        }
        u32 bh[NF][2], bl[NF][2];
#pragma unroll
        for (int nf = 0; nf < NF; nf++) {
            int n0 = wn + nf * 8 + g;
            bh[nf][0] = *(const u32*)&Bh[n0 * 40 + kc];
            bh[nf][1] = *(const u32*)&Bh[n0 * 40 + kc + 8];
            bl[nf][0] = *(const u32*)&Bl[n0 * 40 + kc];
            bl[nf][1] = *(const u32*)&Bl[n0 * 40 + kc + 8];
        }
#pragma unroll
        for (int mf = 0; mf < 4; mf++)
#pragma unroll
            for (int nf = 0; nf < NF; nf++) {
                mma_bf16(acc[mf][nf], ah[mf], bh[nf]);
                mma_bf16(acc[mf][nf], ah[mf], bl[nf]);
                mma_bf16(acc[mf][nf], al[mf], bh[nf]);
            }
    }
}

// ---------------- conversion: fp32 -> bf16 hi/lo ----------------------------
__global__ void conv_k(const float* __restrict__ src, int which, int n) {
    __nv_bfloat16 *dh, *dl;
    if (which == 0) { dh = g_Xh; dl = g_Xl; }
    else { dh = g_Wh + (size_t)(which - 1) * DDIM * DDIM;
           dl = g_Wl + (size_t)(which - 1) * DDIM * DDIM; }
    int i = blockIdx.x * 256 + threadIdx.x;
    if (i < n) {
        float v = src[i];
        __nv_bfloat16 h = __float2bfloat16(v);
        dh[i] = h;
        dl[i] = __float2bfloat16(v - __bfloat162float(h));
    }
}

// ---------------- QKV projections: C = X W^T + b ---------------------------
__global__ __launch_bounds__(256) void qkv_mma(
    const float* __restrict__ bq, const float* __restrict__ bk,
    const float* __restrict__ bv)
{
    extern __shared__ __align__(16) char dsm[];
    __nv_bfloat16* Ah = (__nv_bfloat16*)dsm;
    __nv_bfloat16* Al = Ah + 128 * 40;
    __nv_bfloat16* Bh = Al + 128 * 40;
    __nv_bfloat16* Bl = Bh + 128 * 40;

    int tid = threadIdx.x, wid = tid >> 5, lane = tid & 31;
    int g = lane >> 2, tg = lane & 3;
    int wm = (wid & 1) * 64, wn = (wid >> 1) * 32;
    int z = blockIdx.z, e0 = blockIdx.x * 128, m0 = blockIdx.y * 128;
    const __nv_bfloat16* Wsh = g_Wh + (size_t)z * DDIM * DDIM + (size_t)e0 * DDIM;
    const __nv_bfloat16* Wsl = g_Wl + (size_t)z * DDIM * DDIM + (size_t)e0 * DDIM;
    const __nv_bfloat16* Xh = g_Xh + (size_t)m0 * DDIM;
    const __nv_bfloat16* Xl = g_Xl + (size_t)m0 * DDIM;
    const float* bias = (z == 0) ? bq : (z == 1) ? bk : bv;

    float acc[4][4][4];
#pragma unroll
    for (int a = 0; a < 4; a++)
#pragma unroll
        for (int b = 0; b < 4; b++)
#pragma unroll
            for (int c = 0; c < 4; c++) acc[a][b][c] = 0.f;

    for (int k0 = 0; k0 < DDIM; k0 += 32) {
        ld_tile<128>(Ah, Xh + k0, DDIM);
        ld_tile<128>(Al, Xl + k0, DDIM);
        ld_tile<128>(Bh, Wsh + k0, DDIM);
        ld_tile<128>(Bl, Wsl + k0, DDIM);
        __syncthreads();
        mma_chunk<4>(Ah, Al, Bh, Bl, wm, wn, g, tg, acc);
        __syncthreads();
    }

    u32* stage = (u32*)dsm;
    float sc = (z == 0) ? 0.125f : 1.0f;
#pragma unroll
    for (int mf = 0; mf < 4; mf++)
#pragma unroll
        for (int nf = 0; nf < 4; nf++) {
            int r = wm + mf * 16 + g, c = wn + nf * 8 + tg * 2;
            float b0 = bias[e0 + c], b1 = bias[e0 + c + 1];
            u32 v00 = split_pack((acc[mf][nf][0] + b0) * sc);
            u32 v01 = split_pack((acc[mf][nf][1] + b1) * sc);
            u32 v10 = split_pack((acc[mf][nf][2] + b0) * sc);
            u32 v11 = split_pack((acc[mf][nf][3] + b1) * sc);
            if (z < 2) {
                stage[r * 132 + c] = v00;       stage[r * 132 + c + 1] = v01;
                stage[(r + 8) * 132 + c] = v10; stage[(r + 8) * 132 + c + 1] = v11;
            } else {  // transpose for V
                stage[c * 132 + r] = v00;       stage[(c + 1) * 132 + r] = v01;
                stage[c * 132 + r + 8] = v10;   stage[(c + 1) * 132 + r + 8] = v11;
            }
        }
    __syncthreads();

    int cp = tid & 63;
    if (z < 2) {
        __nv_bfloat16* oh = z ? g_Kh : g_Qh;
        __nv_bfloat16* ol = z ? g_Kl : g_Ql;
        for (int r0 = tid >> 6; r0 < 128; r0 += 4) {
            u32 ua = stage[r0 * 132 + cp * 2], ub = stage[r0 * 132 + cp * 2 + 1];
            u32 hw = (ua & 0xFFFFu) | (ub << 16);
            u32 lw = (ua >> 16) | (ub & 0xFFFF0000u);
            size_t o = (size_t)(m0 + r0) * DDIM + e0 + cp * 2;
            *(u32*)&oh[o] = hw;
            *(u32*)&ol[o] = lw;
        }
    } else {
        int bt = m0 >> 10, n0 = m0 & 1023;
        for (int d0 = tid >> 6; d0 < 128; d0 += 4) {
            u32 ua = stage[d0 * 132 + cp * 2], ub = stage[d0 * 132 + cp * 2 + 1];
            u32 hw = (ua & 0xFFFFu) | (ub << 16);
            u32 lw = (ua >> 16) | (ub & 0xFFFF0000u);
            size_t o = (size_t)(bt * 512 + e0 + d0) * NSEQ + n0 + cp * 2;
            *(u32*)&g_Vth[o] = hw;
            *(u32*)&g_Vtl[o] = lw;
        }
    }
}

// ---------------- S = Q K^T per (bt, head) ---------------------------------
__global__ __launch_bounds__(256) void s_mma()
{
    extern __shared__ __align__(16) char dsm[];
    __nv_bfloat16* Ah = (__nv_bfloat16*)dsm;
    __nv_bfloat16* Al = Ah + 128 * 40;
    __nv_bfloat16* Bh = Al + 128 * 40;
    __nv_bfloat16* Bl = Bh + 128 * 40;

    int tid = threadIdx.x, wid = tid >> 5, lane = tid & 31;
    int g = lane >> 2, tg = lane & 3;
    int wm = (wid & 1) * 64, wn = (wid >> 1) * 32;
    int m0 = blockIdx.x * 128, n0 = blockIdx.y * 128, inst = blockIdx.z;
    int bt = inst >> 3, h = inst & 7;
    const __nv_bfloat16* Qh = g_Qh + (size_t)(bt * NSEQ + m0) * DDIM + h * DH;
    const __nv_bfloat16* Ql = g_Ql + (size_t)(bt * NSEQ + m0) * DDIM + h * DH;
    const __nv_bfloat16* Kh = g_Kh + (size_t)(bt * NSEQ + n0) * DDIM + h * DH;
    const __nv_bfloat16* Kl = g_Kl + (size_t)(bt * NSEQ + n0) * DDIM + h * DH;

    float acc[4][4][4];
#pragma unroll
    for (int a = 0; a < 4; a++)
#pragma unroll
        for (int b = 0; b < 4; b++)
#pragma unroll
            for (int c = 0; c < 4; c++) acc[a][b][c] = 0.f;

    for (int k0 = 0; k0 < DH; k0 += 32) {
        ld_tile<128>(Ah, Qh + k0, DDIM);
        ld_tile<128>(Al, Ql + k0, DDIM);
        ld_tile<128>(Bh, Kh + k0, DDIM);
        ld_tile<128>(Bl, Kl + k0, DDIM);
        __syncthreads();
        mma_chunk<4>(Ah, Al, Bh, Bl, wm, wn, g, tg, acc);
        __syncthreads();
    }

    float* Sp = g_S + (size_t)inst * NSEQ * NSEQ;
#pragma unroll
    for (int mf = 0; mf < 4; mf++)
#pragma unroll
        for (int nf = 0; nf < 4; nf++) {
            int r = m0 + wm + mf * 16 + g, c = n0 + wn + nf * 8 + tg * 2;
            float2 v0 = make_float2(acc[mf][nf][0], acc[mf][nf][1]);
            float2 v1 = make_float2(acc[mf][nf][2], acc[mf][nf][3]);
            *(float2*)&Sp[(size_t)r * NSEQ + c] = v0;
            *(float2*)&Sp[(size_t)(r + 8) * NSEQ + c] = v1;
        }
}

// ---------------- row softmax: S -> P hi/lo --------------------------------
// delta_c bias is constant along the softmax axis -> cancels, omitted.
__global__ __launch_bounds__(128) void softmax_k()
{
    int row = blockIdx.x * 4 + (threadIdx.x >> 5);
    int lane = threadIdx.x & 31;
    size_t rbase = (size_t)row * NSEQ;
    const float* s = g_S + rbase;

    float v[32];
#pragma unroll
    for (int j = 0; j < 8; j++) {
        float4 t = *(const float4*)(s + (size_t)(j * 32 + lane) * 4);
        v[j * 4] = t.x; v[j * 4 + 1] = t.y; v[j * 4 + 2] = t.z; v[j * 4 + 3] = t.w;
    }
    float mx = -1e30f;
#pragma unroll
    for (int i = 0; i < 32; i++) mx = fmaxf(mx, v[i]);
#pragma unroll
    for (int o = 16; o; o >>= 1) mx = fmaxf(mx, __shfl_xor_sync(0xFFFFFFFFu, mx, o));
    float sum = 0.f;
#pragma unroll
    for (int i = 0; i < 32; i++) { v[i] = __expf(v[i] - mx); sum += v[i]; }
#pragma unroll
    for (int o = 16; o; o >>= 1) sum += __shfl_xor_sync(0xFFFFFFFFu, sum, o);
    float inv = 1.f / sum;

    u32* ph = (u32*)(g_Ph + rbase);
    u32* pl = (u32*)(g_Pl + rbase);
#pragma unroll
    for (int j = 0; j < 8; j++) {
        int f = j * 32 + lane;
        u32 hw[2], lw[2];
#pragma unroll
        for (int q = 0; q < 2; q++) {
            u32 a = split_pack(v[j * 4 + 2 * q] * inv);
            u32 b = split_pack(v[j * 4 + 2 * q + 1] * inv);
            hw[q] = (a & 0xFFFFu) | (b << 16);
            lw[q] = (a >> 16) | (b & 0xFFFF0000u);
        }
        ph[f * 2] = hw[0]; ph[f * 2 + 1] = hw[1];
        pl[f * 2] = lw[0]; pl[f * 2 + 1] = lw[1];
    }
}

// ---------------- Z = P V per (bt, head): CTA 128x64 -----------------------
__global__ __launch_bounds__(256) void z_mma()
{
    extern __shared__ __align__(16) char dsm[];
    __nv_bfloat16* Ah = (__nv_bfloat16*)dsm;
    __nv_bfloat16* Al = Ah + 128 * 40;
    __nv_bfloat16* Bh = Al + 128 * 40;
    __nv_bfloat16* Bl = Bh + 64 * 40;

    int tid = threadIdx.x, wid = tid >> 5, lane = tid & 31;
    int g = lane >> 2, tg = lane & 3;
    int wm = (wid & 1) * 64, wn = (wid >> 1) * 16;
    int q0 = blockIdx.x * 128, inst = blockIdx.y;
    int bt = inst >> 3, h = inst & 7;
    const __nv_bfloat16* Ph = g_Ph + (size_t)inst * NSEQ * NSEQ + (size_t)q0 * NSEQ;
    const __nv_bfloat16* Pl = g_Pl + (size_t)inst * NSEQ * NSEQ + (size_t)q0 * NSEQ;
    const __nv_bfloat16* Vh = g_Vth + (size_t)(bt * 512 + h * DH) * NSEQ;
    const __nv_bfloat16* Vl = g_Vtl + (size_t)(bt * 512 + h * DH) * NSEQ;

    float acc[4][2][4];
#pragma unroll
    for (int a = 0; a < 4; a++)
#pragma unroll
        for (int b = 0; b < 2; b++)
#pragma unroll
            for (int c = 0; c < 4; c++) acc[a][b][c] = 0.f;

    for (int k0 = 0; k0 < NSEQ; k0 += 32) {
        ld_tile<128>(Ah, Ph + k0, NSEQ);
        ld_tile<128>(Al, Pl + k0, NSEQ);
        ld_tile<64>(Bh, Vh + k0, NSEQ);
        ld_tile<64>(Bl, Vl + k0, NSEQ);
        __syncthreads();
        mma_chunk<2>(Ah, Al, Bh, Bl, wm, wn, g, tg, acc);
        __syncthreads();
    }

    u32* stage = (u32*)dsm;
#pragma unroll
    for (int mf = 0; mf < 4; mf++)
#pragma unroll
        for (int nf = 0; nf < 2; nf++) {
            int r = wm + mf * 16 + g, c = wn + nf * 8 + tg * 2;
            stage[r * 68 + c]           = split_pack(acc[mf][nf][0]);
            stage[r * 68 + c + 1]       = split_pack(acc[mf][nf][1]);
            stage[(r + 8) * 68 + c]     = split_pack(acc[mf][nf][2]);
            stage[(r + 8) * 68 + c + 1] = split_pack(acc[mf][nf][3]);
        }
    __syncthreads();

    int cp = tid & 31;
    for (int r0 = tid >> 5; r0 < 128; r0 += 8) {
        u32 ua = stage[r0 * 68 + cp * 2], ub = stage[r0 * 68 + cp * 2 + 1];
        u32 hw = (ua & 0xFFFFu) | (ub << 16);
        u32 lw = (ua >> 16) | (ub & 0xFFFF0000u);
        size_t o = (size_t)(bt * NSEQ + q0 + r0) * DDIM + h * DH + cp * 2;
        *(u32*)&g_Zh[o] = hw;
        *(u32*)&g_Zl[o] = lw;
    }
}

// ---------------- out = Z Wo^T + bo ----------------------------------------
__global__ __launch_bounds__(256) void out_mma(const float* __restrict__ bo,
                                               float* __restrict__ out)
{
    extern __shared__ __align__(16) char dsm[];
    __nv_bfloat16* Ah = (__nv_bfloat16*)dsm;
    __nv_bfloat16* Al = Ah + 128 * 40;
    __nv_bfloat16* Bh = Al + 128 * 40;
    __nv_bfloat16* Bl = Bh + 128 * 40;

    int tid = threadIdx.x, wid = tid >> 5, lane = tid & 31;
    int g = lane >> 2, tg = lane & 3;
    int wm = (wid & 1) * 64, wn = (wid >> 1) * 32;
    int e0 = blockIdx.x * 128, m0 = blockIdx.y * 128;
    const __nv_bfloat16* Wsh = g_Wh + (size_t)3 * DDIM * DDIM + (size_t)e0 * DDIM;
    const __nv_bfloat16* Wsl = g_Wl + (size_t)3 * DDIM * DDIM + (size_t)e0 * DDIM;
    const __nv_bfloat16* Zh = g_Zh + (size_t)m0 * DDIM;
    const __nv_bfloat16* Zl = g_Zl + (size_t)m0 * DDIM;

    float acc[4][4][4];
#pragma unroll
    for (int a = 0; a < 4; a++)
#pragma unroll
        for (int b = 0; b < 4; b++)
#pragma unroll
            for (int c = 0; c < 4; c++) acc[a][b][c] = 0.f;

    for (int k0 = 0; k0 < DDIM; k0 += 32) {
        ld_tile<128>(Ah, Zh + k0, DDIM);
        ld_tile<128>(Al, Zl + k0, DDIM);
        ld_tile<128>(Bh, Wsh + k0, DDIM);
        ld_tile<128>(Bl, Wsl + k0, DDIM);
        __syncthreads();
        mma_chunk<4>(Ah, Al, Bh, Bl, wm, wn, g, tg, acc);
        __syncthreads();
    }

    float* stage = (float*)dsm;
#pragma unroll
    for (int mf = 0; mf < 4; mf++)
#pragma unroll
        for (int nf = 0; nf < 4; nf++) {
            int r = wm + mf * 16 + g, c = wn + nf * 8 + tg * 2;
            float b0 = bo[e0 + c], b1 = bo[e0 + c + 1];
            stage[r * 132 + c]           = acc[mf][nf][0] + b0;
            stage[r * 132 + c + 1]       = acc[mf][nf][1] + b1;
            stage[(r + 8) * 132 + c]     = acc[mf][nf][2] + b0;
            stage[(r + 8) * 132 + c + 1] = acc[mf][nf][3] + b1;
        }
    __syncthreads();

    int cp = tid & 63;
    for (int r0 = tid >> 6; r0 < 128; r0 += 4) {
        float2 v = make_float2(stage[r0 * 132 + cp * 2], stage[r0 * 132 + cp * 2 + 1]);
        *(float2*)&out[(size_t)(m0 + r0) * DDIM + e0 + cp * 2] = v;
    }
}

// ---------------- launch ----------------------------------------------------
extern "C" void kernel_launch(void* const* d_in, const int* in_sizes, int n_in,
                              void* d_out, int out_size)
{
    const float* X  = (const float*)d_in[0];
    const float* Wq = (const float*)d_in[1];
    const float* bq = (const float*)d_in[2];
    const float* Wk = (const float*)d_in[3];
    const float* bk = (const float*)d_in[4];
    const float* Wv = (const float*)d_in[5];
    const float* bv = (const float*)d_in[6];
    const float* Wo = (const float*)d_in[7];
    const float* bo = (const float*)d_in[8];
    float* out = (float*)d_out;

    static int inited = 0;
    if (!inited) {
        cudaFuncSetAttribute(qkv_mma, cudaFuncAttributeMaxDynamicSharedMemorySize, 69632);
        cudaFuncSetAttribute(s_mma,   cudaFuncAttributeMaxDynamicSharedMemorySize, 69632);
        cudaFuncSetAttribute(z_mma,   cudaFuncAttributeMaxDynamicSharedMemorySize, 69632);
        cudaFuncSetAttribute(out_mma, cudaFuncAttributeMaxDynamicSharedMemorySize, 69632);
        inited = 1;
    }

    int nX = MTOT * DDIM, nW = DDIM * DDIM;
    conv_k<<<(nX + 255) / 256, 256>>>(X, 0, nX);
    conv_k<<<(nW + 255) / 256, 256>>>(Wq, 1, nW);
    conv_k<<<(nW + 255) / 256, 256>>>(Wk, 2, nW);
    conv_k<<<(nW + 255) / 256, 256>>>(Wv, 3, nW);
    conv_k<<<(nW + 255) / 256, 256>>>(Wo, 4, nW);

    qkv_mma<<<dim3(4, 128, 3), 256, 69632>>>(bq, bk, bv);
    s_mma<<<dim3(8, 8, NINST), 256, 40960>>>();
    softmax_k<<<NINST * NSEQ / 4, 128>>>();
    z_mma<<<dim3(8, NINST), 256, 40960>>>();
    out_mma<<<dim3(4, 128), 256, 69632>>>(bo, out);
}

// round 6
// speedup vs baseline: 2.7898x; 1.3238x over previous
#include <cuda_runtime.h>
#include <cuda_bf16.h>
#include <stdint.h>

typedef uint32_t u32;
typedef unsigned short u16;

#define MTOT 16384   // B*T*N
#define DDIM 512
#define NSEQ 1024
#define DH 64
#define NINST 128    // (B*T)*HEADS

// ---------------- scratch (device globals; no allocation allowed) ----------
__device__ __nv_bfloat16 g_Xh[MTOT*DDIM], g_Xl[MTOT*DDIM];
__device__ __nv_bfloat16 g_Wh[4*DDIM*DDIM], g_Wl[4*DDIM*DDIM];
__device__ __nv_bfloat16 g_Qh[MTOT*DDIM], g_Ql[MTOT*DDIM];
__device__ __nv_bfloat16 g_Kh[MTOT*DDIM], g_Kl[MTOT*DDIM];
__device__ __nv_bfloat16 g_Vth[MTOT*DDIM], g_Vtl[MTOT*DDIM];  // V transposed [d, n]
__device__ __nv_bfloat16 g_Zh[MTOT*DDIM], g_Zl[MTOT*DDIM];

// ---------------- helpers ---------------------------------------------------
__device__ __forceinline__ void mma_bf16(float* c, const u32* a, const u32* b) {
    asm volatile(
        "mma.sync.aligned.m16n8k16.row.col.f32.bf16.bf16.f32 "
        "{%0,%1,%2,%3}, {%4,%5,%6,%7}, {%8,%9}, {%0,%1,%2,%3};"
        : "+f"(c[0]), "+f"(c[1]), "+f"(c[2]), "+f"(c[3])
        : "r"(a[0]), "r"(a[1]), "r"(a[2]), "r"(a[3]), "r"(b[0]), "r"(b[1]));
}

__device__ __forceinline__ u32 split_pack(float v) {
    __nv_bfloat16 h = __float2bfloat16(v);
    float r = v - __bfloat162float(h);
    __nv_bfloat16 l = __float2bfloat16(r);
    return (u32)__bfloat16_as_ushort(h) | ((u32)__bfloat16_as_ushort(l) << 16);
}
// pack two floats -> (hi-pair, lo-pair) bf16x2 words
__device__ __forceinline__ void split_pair(float x0, float x1, u32& hw, u32& lw) {
    __nv_bfloat162 h = __floats2bfloat162_rn(x0, x1);
    float r0 = x0 - __bfloat162float(h.x);
    float r1 = x1 - __bfloat162float(h.y);
    __nv_bfloat162 l = __floats2bfloat162_rn(r0, r1);
    hw = *(u32*)&h;
    lw = *(u32*)&l;
}

// load ROWS x 32 bf16 tile into smem (stride 40 elems), 256 threads
template<int ROWS>
__device__ __forceinline__ void ld_tile(__nv_bfloat16* dst, const __nv_bfloat16* src, int ld) {
    int t = threadIdx.x;
#pragma unroll
    for (int i = t; i < ROWS * 2; i += 256) {
        int r = i >> 1, c = (i & 1) * 16;
        const uint4* s = (const uint4*)(src + (size_t)r * ld + c);
        uint4* d = (uint4*)(dst + r * 40 + c);
        d[0] = s[0]; d[1] = s[1];
    }
}

// one K=32 chunk of 3-pass bf16 mma. Warp tile 64 x (8*NF).
template<int NF>
__device__ __forceinline__ void mma_chunk(
    const __nv_bfloat16* Ah, const __nv_bfloat16* Al,
    const __nv_bfloat16* Bh, const __nv_bfloat16* Bl,
    int wm, int wn, int g, int tg, float acc[4][NF][4])
{
#pragma unroll
    for (int s = 0; s < 2; s++) {
        int kc = s * 16 + tg * 2;
        u32 ah[4][4], al[4][4];
#pragma unroll
        for (int mf = 0; mf < 4; mf++) {
            int r0 = wm + mf * 16 + g;
            ah[mf][0] = *(const u32*)&Ah[r0 * 40 + kc];
            ah[mf][1] = *(const u32*)&Ah[(r0 + 8) * 40 + kc];
            ah[mf][2] = *(const u32*)&Ah[r0 * 40 + kc + 8];
            ah[mf][3] = *(const u32*)&Ah[(r0 + 8) * 40 + kc + 8];
            al[mf][0] = *(const u32*)&Al[r0 * 40 + kc];
            al[mf][1] = *(const u32*)&Al[(r0 + 8) * 40 + kc];
            al[mf][2] = *(const u32*)&Al[r0 * 40 + kc + 8];
            al[mf][3] = *(const u32*)&Al[(r0 + 8) * 40 + kc + 8];
        }
        u32 bh[NF][2], bl[NF][2];
#pragma unroll
        for (int nf = 0; nf < NF; nf++) {
            int n0 = wn + nf * 8 + g;
            bh[nf][0] = *(const u32*)&Bh[n0 * 40 + kc];
            bh[nf][1] = *(const u32*)&Bh[n0 * 40 + kc + 8];
            bl[nf][0] = *(const u32*)&Bl[n0 * 40 + kc];
            bl[nf][1] = *(const u32*)&Bl[n0 * 40 + kc + 8];
        }
#pragma unroll
        for (int mf = 0; mf < 4; mf++)
#pragma unroll
            for (int nf = 0; nf < NF; nf++) {
                mma_bf16(acc[mf][nf], ah[mf], bh[nf]);
                mma_bf16(acc[mf][nf], ah[mf], bl[nf]);
                mma_bf16(acc[mf][nf], al[mf], bh[nf]);
            }
    }
}

// ---------------- conversion: fp32 -> bf16 hi/lo ----------------------------
__global__ void conv_k(const float* __restrict__ src, int which, int n) {
    __nv_bfloat16 *dh, *dl;
    if (which == 0) { dh = g_Xh; dl = g_Xl; }
    else { dh = g_Wh + (size_t)(which - 1) * DDIM * DDIM;
           dl = g_Wl + (size_t)(which - 1) * DDIM * DDIM; }
    int i = blockIdx.x * 256 + threadIdx.x;
    if (i < n) {
        float v = src[i];
        __nv_bfloat16 h = __float2bfloat16(v);
        dh[i] = h;
        dl[i] = __float2bfloat16(v - __bfloat162float(h));
    }
}

// ---------------- QKV projections: C = X W^T + b ---------------------------
__global__ __launch_bounds__(256) void qkv_mma(
    const float* __restrict__ bq, const float* __restrict__ bk,
    const float* __restrict__ bv)
{
    extern __shared__ __align__(16) char dsm[];
    __nv_bfloat16* Ah = (__nv_bfloat16*)dsm;
    __nv_bfloat16* Al = Ah + 128 * 40;
    __nv_bfloat16* Bh = Al + 128 * 40;
    __nv_bfloat16* Bl = Bh + 128 * 40;

    int tid = threadIdx.x, wid = tid >> 5, lane = tid & 31;
    int g = lane >> 2, tg = lane & 3;
    int wm = (wid & 1) * 64, wn = (wid >> 1) * 32;
    int z = blockIdx.z, e0 = blockIdx.x * 128, m0 = blockIdx.y * 128;
    const __nv_bfloat16* Wsh = g_Wh + (size_t)z * DDIM * DDIM + (size_t)e0 * DDIM;
    const __nv_bfloat16* Wsl = g_Wl + (size_t)z * DDIM * DDIM + (size_t)e0 * DDIM;
    const __nv_bfloat16* Xh = g_Xh + (size_t)m0 * DDIM;
    const __nv_bfloat16* Xl = g_Xl + (size_t)m0 * DDIM;
    const float* bias = (z == 0) ? bq : (z == 1) ? bk : bv;

    float acc[4][4][4];
#pragma unroll
    for (int a = 0; a < 4; a++)
#pragma unroll
        for (int b = 0; b < 4; b++)
#pragma unroll
            for (int c = 0; c < 4; c++) acc[a][b][c] = 0.f;

    for (int k0 = 0; k0 < DDIM; k0 += 32) {
        ld_tile<128>(Ah, Xh + k0, DDIM);
        ld_tile<128>(Al, Xl + k0, DDIM);
        ld_tile<128>(Bh, Wsh + k0, DDIM);
        ld_tile<128>(Bl, Wsl + k0, DDIM);
        __syncthreads();
        mma_chunk<4>(Ah, Al, Bh, Bl, wm, wn, g, tg, acc);
        __syncthreads();
    }

    u32* stage = (u32*)dsm;
    float sc = (z == 0) ? 0.125f : 1.0f;
#pragma unroll
    for (int mf = 0; mf < 4; mf++)
#pragma unroll
        for (int nf = 0; nf < 4; nf++) {
            int r = wm + mf * 16 + g, c = wn + nf * 8 + tg * 2;
            float b0 = bias[e0 + c], b1 = bias[e0 + c + 1];
            u32 v00 = split_pack((acc[mf][nf][0] + b0) * sc);
            u32 v01 = split_pack((acc[mf][nf][1] + b1) * sc);
            u32 v10 = split_pack((acc[mf][nf][2] + b0) * sc);
            u32 v11 = split_pack((acc[mf][nf][3] + b1) * sc);
            if (z < 2) {
                stage[r * 132 + c] = v00;       stage[r * 132 + c + 1] = v01;
                stage[(r + 8) * 132 + c] = v10; stage[(r + 8) * 132 + c + 1] = v11;
            } else {  // transpose for V
                stage[c * 132 + r] = v00;       stage[(c + 1) * 132 + r] = v01;
                stage[c * 132 + r + 8] = v10;   stage[(c + 1) * 132 + r + 8] = v11;
            }
        }
    __syncthreads();

    int cp = tid & 63;
    if (z < 2) {
        __nv_bfloat16* oh = z ? g_Kh : g_Qh;
        __nv_bfloat16* ol = z ? g_Kl : g_Ql;
        for (int r0 = tid >> 6; r0 < 128; r0 += 4) {
            u32 ua = stage[r0 * 132 + cp * 2], ub = stage[r0 * 132 + cp * 2 + 1];
            u32 hw = (ua & 0xFFFFu) | (ub << 16);
            u32 lw = (ua >> 16) | (ub & 0xFFFF0000u);
            size_t o = (size_t)(m0 + r0) * DDIM + e0 + cp * 2;
            *(u32*)&oh[o] = hw;
            *(u32*)&ol[o] = lw;
        }
    } else {
        int bt = m0 >> 10, n0 = m0 & 1023;
        for (int d0 = tid >> 6; d0 < 128; d0 += 4) {
            u32 ua = stage[d0 * 132 + cp * 2], ub = stage[d0 * 132 + cp * 2 + 1];
            u32 hw = (ua & 0xFFFFu) | (ub << 16);
            u32 lw = (ua >> 16) | (ub & 0xFFFF0000u);
            size_t o = (size_t)(bt * 512 + e0 + d0) * NSEQ + n0 + cp * 2;
            *(u32*)&g_Vth[o] = hw;
            *(u32*)&g_Vtl[o] = lw;
        }
    }
}

// ---------------- fused flash attention: Z = softmax(QK^T) V ---------------
// One CTA = 128 query rows of one (bt, head). 8 warps x 16 rows each.
// delta_c bias is constant along the softmax axis -> cancels, omitted.
#define KSTR 72     // K smem row stride (bf16 elems)
#define VSTR 136    // Vt smem row stride
#define FA_SMEM (2*128*KSTR*2 + 2*64*VSTR*2)   // 36864 + 34816 = 71680

__global__ __launch_bounds__(256) void fattn()
{
    extern __shared__ __align__(16) char dsm[];
    __nv_bfloat16* Kh = (__nv_bfloat16*)dsm;
    __nv_bfloat16* Kl = Kh + 128 * KSTR;
    __nv_bfloat16* Vh = Kl + 128 * KSTR;
    __nv_bfloat16* Vl = Vh + 64 * VSTR;

    int tid = threadIdx.x, wid = tid >> 5, lane = tid & 31;
    int g = lane >> 2, tg = lane & 3;
    int wm = wid * 16;
    int q0 = blockIdx.x * 128, inst = blockIdx.y;
    int bt = inst >> 3, h = inst & 7;

    const __nv_bfloat16* Qhp = g_Qh + (size_t)(bt * NSEQ + q0) * DDIM + h * DH;
    const __nv_bfloat16* Qlp = g_Ql + (size_t)(bt * NSEQ + q0) * DDIM + h * DH;
    const __nv_bfloat16* Khp = g_Kh + (size_t)(bt * NSEQ) * DDIM + h * DH;
    const __nv_bfloat16* Klp = g_Kl + (size_t)(bt * NSEQ) * DDIM + h * DH;
    const __nv_bfloat16* Vhp = g_Vth + (size_t)(bt * 512 + h * DH) * NSEQ;
    const __nv_bfloat16* Vlp = g_Vtl + (size_t)(bt * 512 + h * DH) * NSEQ;

    // ---- stage Q tile (reuse K area), extract fragments ----
    {
        int r = tid >> 1, c = (tid & 1) * 32;
#pragma unroll
        for (int p = 0; p < 4; p++) {
            *(uint4*)(Kh + r * KSTR + c + p * 8) = *(const uint4*)(Qhp + (size_t)r * DDIM + c + p * 8);
            *(uint4*)(Kl + r * KSTR + c + p * 8) = *(const uint4*)(Qlp + (size_t)r * DDIM + c + p * 8);
        }
    }
    __syncthreads();
    u32 qh[4][4], ql[4][4];
#pragma unroll
    for (int kc = 0; kc < 4; kc++) {
        int k0 = kc * 16 + tg * 2;
        qh[kc][0] = *(const u32*)&Kh[(wm + g) * KSTR + k0];
        qh[kc][1] = *(const u32*)&Kh[(wm + g + 8) * KSTR + k0];
        qh[kc][2] = *(const u32*)&Kh[(wm + g) * KSTR + k0 + 8];
        qh[kc][3] = *(const u32*)&Kh[(wm + g + 8) * KSTR + k0 + 8];
        ql[kc][0] = *(const u32*)&Kl[(wm + g) * KSTR + k0];
        ql[kc][1] = *(const u32*)&Kl[(wm + g + 8) * KSTR + k0];
        ql[kc][2] = *(const u32*)&Kl[(wm + g) * KSTR + k0 + 8];
        ql[kc][3] = *(const u32*)&Kl[(wm + g + 8) * KSTR + k0 + 8];
    }
    __syncthreads();

    float mA = -1e30f, mB = -1e30f, lA = 0.f, lB = 0.f;
    float zacc[8][4];
#pragma unroll
    for (int n = 0; n < 8; n++)
#pragma unroll
        for (int c = 0; c < 4; c++) zacc[n][c] = 0.f;

    for (int j0 = 0; j0 < NSEQ; j0 += 128) {
        // ---- load K (128x64 hi/lo) and Vt (64x128 hi/lo) tiles ----
        {
            int r = tid >> 1, c = (tid & 1) * 32;
#pragma unroll
            for (int p = 0; p < 4; p++) {
                *(uint4*)(Kh + r * KSTR + c + p * 8) =
                    *(const uint4*)(Khp + (size_t)(j0 + r) * DDIM + c + p * 8);
                *(uint4*)(Kl + r * KSTR + c + p * 8) =
                    *(const uint4*)(Klp + (size_t)(j0 + r) * DDIM + c + p * 8);
            }
            int d = tid >> 2, cv = (tid & 3) * 32;
#pragma unroll
            for (int p = 0; p < 4; p++) {
                *(uint4*)(Vh + d * VSTR + cv + p * 8) =
                    *(const uint4*)(Vhp + (size_t)d * NSEQ + j0 + cv + p * 8);
                *(uint4*)(Vl + d * VSTR + cv + p * 8) =
                    *(const uint4*)(Vlp + (size_t)d * NSEQ + j0 + cv + p * 8);
            }
        }
        __syncthreads();

        // ---- S = Q K^T : 16 key-frags x 4 k-chunks, 3-pass ----
        float sacc[16][4];
#pragma unroll
        for (int n = 0; n < 16; n++)
#pragma unroll
            for (int c = 0; c < 4; c++) sacc[n][c] = 0.f;
#pragma unroll
        for (int kc = 0; kc < 4; kc++) {
            int k0 = kc * 16 + tg * 2;
#pragma unroll
            for (int nf = 0; nf < 16; nf++) {
                int n0 = nf * 8 + g;
                u32 bh[2], bl[2];
                bh[0] = *(const u32*)&Kh[n0 * KSTR + k0];
                bh[1] = *(const u32*)&Kh[n0 * KSTR + k0 + 8];
                bl[0] = *(const u32*)&Kl[n0 * KSTR + k0];
                bl[1] = *(const u32*)&Kl[n0 * KSTR + k0 + 8];
                mma_bf16(sacc[nf], qh[kc], bh);
                mma_bf16(sacc[nf], qh[kc], bl);
                mma_bf16(sacc[nf], ql[kc], bh);
            }
        }

        // ---- online softmax (rows g and g+8 of this warp tile) ----
        float nmA = mA, nmB = mB;
#pragma unroll
        for (int nf = 0; nf < 16; nf++) {
            nmA = fmaxf(nmA, fmaxf(sacc[nf][0], sacc[nf][1]));
            nmB = fmaxf(nmB, fmaxf(sacc[nf][2], sacc[nf][3]));
        }
#pragma unroll
        for (int o = 1; o <= 2; o <<= 1) {
            nmA = fmaxf(nmA, __shfl_xor_sync(0xFFFFFFFFu, nmA, o));
            nmB = fmaxf(nmB, __shfl_xor_sync(0xFFFFFFFFu, nmB, o));
        }
        float corrA = __expf(mA - nmA), corrB = __expf(mB - nmB);
        mA = nmA; mB = nmB;

        float sA = 0.f, sB = 0.f;
#pragma unroll
        for (int nf = 0; nf < 16; nf++) {
            sacc[nf][0] = __expf(sacc[nf][0] - nmA);
            sacc[nf][1] = __expf(sacc[nf][1] - nmA);
            sacc[nf][2] = __expf(sacc[nf][2] - nmB);
            sacc[nf][3] = __expf(sacc[nf][3] - nmB);
            sA += sacc[nf][0] + sacc[nf][1];
            sB += sacc[nf][2] + sacc[nf][3];
        }
#pragma unroll
        for (int o = 1; o <= 2; o <<= 1) {
            sA += __shfl_xor_sync(0xFFFFFFFFu, sA, o);
            sB += __shfl_xor_sync(0xFFFFFFFFu, sB, o);
        }
        lA = lA * corrA + sA;
        lB = lB * corrB + sB;

#pragma unroll
        for (int n = 0; n < 8; n++) {
            zacc[n][0] *= corrA; zacc[n][1] *= corrA;
            zacc[n][2] *= corrB; zacc[n][3] *= corrB;
        }

        // ---- Z += P V : repack S-frags as A-frags, 8 key-chunks ----
#pragma unroll
        for (int kc2 = 0; kc2 < 8; kc2++) {
            u32 ah[4], al[4];
            split_pair(sacc[2*kc2][0],   sacc[2*kc2][1],   ah[0], al[0]);
            split_pair(sacc[2*kc2][2],   sacc[2*kc2][3],   ah[1], al[1]);
            split_pair(sacc[2*kc2+1][0], sacc[2*kc2+1][1], ah[2], al[2]);
            split_pair(sacc[2*kc2+1][2], sacc[2*kc2+1][3], ah[3], al[3]);
            int k0 = kc2 * 16 + tg * 2;
#pragma unroll
            for (int nf = 0; nf < 8; nf++) {
                int n0 = nf * 8 + g;
                u32 bh[2], bl[2];
                bh[0] = *(const u32*)&Vh[n0 * VSTR + k0];
                bh[1] = *(const u32*)&Vh[n0 * VSTR + k0 + 8];
                bl[0] = *(const u32*)&Vl[n0 * VSTR + k0];
                bl[1] = *(const u32*)&Vl[n0 * VSTR + k0 + 8];
                mma_bf16(zacc[nf], ah, bh);
                mma_bf16(zacc[nf], ah, bl);
                mma_bf16(zacc[nf], al, bh);
            }
        }
        __syncthreads();
    }

    // ---- epilogue: Z /= l, store bf16 hi/lo ----
    float invA = 1.f / lA, invB = 1.f / lB;
    size_t rowA = (size_t)(bt * NSEQ + q0 + wm + g) * DDIM + h * DH;
    size_t rowB = rowA + 8 * DDIM;
#pragma unroll
    for (int nf = 0; nf < 8; nf++) {
        int c = nf * 8 + tg * 2;
        u32 hw, lw;
        split_pair(zacc[nf][0] * invA, zacc[nf][1] * invA, hw, lw);
        *(u32*)&g_Zh[rowA + c] = hw;
        *(u32*)&g_Zl[rowA + c] = lw;
        split_pair(zacc[nf][2] * invB, zacc[nf][3] * invB, hw, lw);
        *(u32*)&g_Zh[rowB + c] = hw;
        *(u32*)&g_Zl[rowB + c] = lw;
    }
}

// ---------------- out = Z Wo^T + bo ----------------------------------------
__global__ __launch_bounds__(256) void out_mma(const float* __restrict__ bo,
                                               float* __restrict__ out)
{
    extern __shared__ __align__(16) char dsm[];
    __nv_bfloat16* Ah = (__nv_bfloat16*)dsm;
    __nv_bfloat16* Al = Ah + 128 * 40;
    __nv_bfloat16* Bh = Al + 128 * 40;
    __nv_bfloat16* Bl = Bh + 128 * 40;

    int tid = threadIdx.x, wid = tid >> 5, lane = tid & 31;
    int g = lane >> 2, tg = lane & 3;
    int wm = (wid & 1) * 64, wn = (wid >> 1) * 32;
    int e0 = blockIdx.x * 128, m0 = blockIdx.y * 128;
    const __nv_bfloat16* Wsh = g_Wh + (size_t)3 * DDIM * DDIM + (size_t)e0 * DDIM;
    const __nv_bfloat16* Wsl = g_Wl + (size_t)3 * DDIM * DDIM + (size_t)e0 * DDIM;
    const __nv_bfloat16* Zh = g_Zh + (size_t)m0 * DDIM;
    const __nv_bfloat16* Zl = g_Zl + (size_t)m0 * DDIM;

    float acc[4][4][4];
#pragma unroll
    for (int a = 0; a < 4; a++)
#pragma unroll
        for (int b = 0; b < 4; b++)
#pragma unroll
            for (int c = 0; c < 4; c++) acc[a][b][c] = 0.f;

    for (int k0 = 0; k0 < DDIM; k0 += 32) {
        ld_tile<128>(Ah, Zh + k0, DDIM);
        ld_tile<128>(Al, Zl + k0, DDIM);
        ld_tile<128>(Bh, Wsh + k0, DDIM);
        ld_tile<128>(Bl, Wsl + k0, DDIM);
        __syncthreads();
        mma_chunk<4>(Ah, Al, Bh, Bl, wm, wn, g, tg, acc);
        __syncthreads();
    }

    float* stage = (float*)dsm;
#pragma unroll
    for (int mf = 0; mf < 4; mf++)
#pragma unroll
        for (int nf = 0; nf < 4; nf++) {
            int r = wm + mf * 16 + g, c = wn + nf * 8 + tg * 2;
            float b0 = bo[e0 + c], b1 = bo[e0 + c + 1];
            stage[r * 132 + c]           = acc[mf][nf][0] + b0;
            stage[r * 132 + c + 1]       = acc[mf][nf][1] + b1;
            stage[(r + 8) * 132 + c]     = acc[mf][nf][2] + b0;
            stage[(r + 8) * 132 + c + 1] = acc[mf][nf][3] + b1;
        }
    __syncthreads();

    int cp = tid & 63;
    for (int r0 = tid >> 6; r0 < 128; r0 += 4) {
        float2 v = make_float2(stage[r0 * 132 + cp * 2], stage[r0 * 132 + cp * 2 + 1]);
        *(float2*)&out[(size_t)(m0 + r0) * DDIM + e0 + cp * 2] = v;
    }
}

// ---------------- launch ----------------------------------------------------
extern "C" void kernel_launch(void* const* d_in, const int* in_sizes, int n_in,
                              void* d_out, int out_size)
{
    const float* X  = (const float*)d_in[0];
    const float* Wq = (const float*)d_in[1];
    const float* bq = (const float*)d_in[2];
    const float* Wk = (const float*)d_in[3];
    const float* bk = (const float*)d_in[4];
    const float* Wv = (const float*)d_in[5];
    const float* bv = (const float*)d_in[6];
    const float* Wo = (const float*)d_in[7];
    const float* bo = (const float*)d_in[8];
    float* out = (float*)d_out;

    cudaFuncSetAttribute(qkv_mma, cudaFuncAttributeMaxDynamicSharedMemorySize, 69632);
    cudaFuncSetAttribute(fattn,   cudaFuncAttributeMaxDynamicSharedMemorySize, FA_SMEM);
    cudaFuncSetAttribute(out_mma, cudaFuncAttributeMaxDynamicSharedMemorySize, 69632);

    int nX = MTOT * DDIM, nW = DDIM * DDIM;
    conv_k<<<(nX + 255) / 256, 256>>>(X, 0, nX);
    conv_k<<<(nW + 255) / 256, 256>>>(Wq, 1, nW);
    conv_k<<<(nW + 255) / 256, 256>>>(Wk, 2, nW);
    conv_k<<<(nW + 255) / 256, 256>>>(Wv, 3, nW);
    conv_k<<<(nW + 255) / 256, 256>>>(Wo, 4, nW);

    qkv_mma<<<dim3(4, 128, 3), 256, 69632>>>(bq, bk, bv);
    fattn<<<dim3(NSEQ / 128, NINST), 256, FA_SMEM>>>();
    out_mma<<<dim3(4, 128), 256, 69632>>>(bo, out);
}

// round 7
// speedup vs baseline: 3.6904x; 1.3229x over previous
#include <cuda_runtime.h>
#include <cuda_bf16.h>
#include <stdint.h>

typedef uint32_t u32;
typedef unsigned short u16;

#define MTOT 16384   // B*T*N
#define DDIM 512
#define NSEQ 1024
#define DH 64
#define NINST 128    // (B*T)*HEADS

// ---------------- scratch (device globals; no allocation allowed) ----------
__device__ __nv_bfloat16 g_Xh[MTOT*DDIM], g_Xl[MTOT*DDIM];
__device__ __nv_bfloat16 g_Wh[4*DDIM*DDIM], g_Wl[4*DDIM*DDIM];
__device__ __nv_bfloat16 g_Qh[MTOT*DDIM], g_Ql[MTOT*DDIM];
__device__ __nv_bfloat16 g_Kh[MTOT*DDIM], g_Kl[MTOT*DDIM];
__device__ __nv_bfloat16 g_Vth[MTOT*DDIM], g_Vtl[MTOT*DDIM];  // V transposed [d, n]
__device__ __nv_bfloat16 g_Zh[MTOT*DDIM], g_Zl[MTOT*DDIM];

// ---------------- helpers ---------------------------------------------------
__device__ __forceinline__ void mma_bf16(float* c, const u32* a, const u32* b) {
    asm volatile(
        "mma.sync.aligned.m16n8k16.row.col.f32.bf16.bf16.f32 "
        "{%0,%1,%2,%3}, {%4,%5,%6,%7}, {%8,%9}, {%0,%1,%2,%3};"
        : "+f"(c[0]), "+f"(c[1]), "+f"(c[2]), "+f"(c[3])
        : "r"(a[0]), "r"(a[1]), "r"(a[2]), "r"(a[3]), "r"(b[0]), "r"(b[1]));
}

__device__ __forceinline__ void cp16(u32 dst, const void* src) {
    asm volatile("cp.async.cg.shared.global [%0], [%1], 16;" :: "r"(dst), "l"(src));
}
__device__ __forceinline__ void cp_commit() {
    asm volatile("cp.async.commit_group;" ::: "memory");
}
template<int N>
__device__ __forceinline__ void cp_wait() {
    asm volatile("cp.async.wait_group %0;" :: "n"(N) : "memory");
}

__device__ __forceinline__ u32 split_pack(float v) {
    __nv_bfloat16 h = __float2bfloat16(v);
    float r = v - __bfloat162float(h);
    __nv_bfloat16 l = __float2bfloat16(r);
    return (u32)__bfloat16_as_ushort(h) | ((u32)__bfloat16_as_ushort(l) << 16);
}
__device__ __forceinline__ void split_pair(float x0, float x1, u32& hw, u32& lw) {
    __nv_bfloat162 h = __floats2bfloat162_rn(x0, x1);
    float r0 = x0 - __bfloat162float(h.x);
    float r1 = x1 - __bfloat162float(h.y);
    __nv_bfloat162 l = __floats2bfloat162_rn(r0, r1);
    hw = *(u32*)&h;
    lw = *(u32*)&l;
}

#define TS 5120   // 128*40 elems per tile

// async-copy a 128x32 bf16 tile (row stride ld) into smem (stride 40)
__device__ __forceinline__ void cp_tile128(u32 dst, const __nv_bfloat16* src, int ld) {
    int t = threadIdx.x;
#pragma unroll
    for (int i = t; i < 512; i += 256) {
        int r = i >> 2, c = (i & 3) * 8;
        cp16(dst + (u32)(r * 40 + c) * 2, src + (size_t)r * ld + c);
    }
}

// one K=32 chunk of 3-pass bf16 mma. Warp tile 64 x (8*NF).
template<int NF>
__device__ __forceinline__ void mma_chunk(
    const __nv_bfloat16* Ah, const __nv_bfloat16* Al,
    const __nv_bfloat16* Bh, const __nv_bfloat16* Bl,
    int wm, int wn, int g, int tg, float acc[4][NF][4])
{
#pragma unroll
    for (int s = 0; s < 2; s++) {
        int kc = s * 16 + tg * 2;
        u32 ah[4][4], al[4][4];
#pragma unroll
        for (int mf = 0; mf < 4; mf++) {
            int r0 = wm + mf * 16 + g;
            ah[mf][0] = *(const u32*)&Ah[r0 * 40 + kc];
            ah[mf][1] = *(const u32*)&Ah[(r0 + 8) * 40 + kc];
            ah[mf][2] = *(const u32*)&Ah[r0 * 40 + kc + 8];
            ah[mf][3] = *(const u32*)&Ah[(r0 + 8) * 40 + kc + 8];
            al[mf][0] = *(const u32*)&Al[r0 * 40 + kc];
            al[mf][1] = *(const u32*)&Al[(r0 + 8) * 40 + kc];
            al[mf][2] = *(const u32*)&Al[r0 * 40 + kc + 8];
            al[mf][3] = *(const u32*)&Al[(r0 + 8) * 40 + kc + 8];
        }
        u32 bh[NF][2], bl[NF][2];
#pragma unroll
        for (int nf = 0; nf < NF; nf++) {
            int n0 = wn + nf * 8 + g;
            bh[nf][0] = *(const u32*)&Bh[n0 * 40 + kc];
            bh[nf][1] = *(const u32*)&Bh[n0 * 40 + kc + 8];
            bl[nf][0] = *(const u32*)&Bl[n0 * 40 + kc];
            bl[nf][1] = *(const u32*)&Bl[n0 * 40 + kc + 8];
        }
#pragma unroll
        for (int mf = 0; mf < 4; mf++)
#pragma unroll
            for (int nf = 0; nf < NF; nf++) {
                mma_bf16(acc[mf][nf], ah[mf], bh[nf]);
                mma_bf16(acc[mf][nf], ah[mf], bl[nf]);
                mma_bf16(acc[mf][nf], al[mf], bh[nf]);
            }
    }
}

// ---------------- conversion: fp32 -> bf16 hi/lo ----------------------------
__global__ void conv_x(const float* __restrict__ src, int n) {
    int i = blockIdx.x * 256 + threadIdx.x;
    if (i < n) {
        float v = src[i];
        __nv_bfloat16 h = __float2bfloat16(v);
        g_Xh[i] = h;
        g_Xl[i] = __float2bfloat16(v - __bfloat162float(h));
    }
}
__global__ void conv_w(const float* __restrict__ wq, const float* __restrict__ wk,
                       const float* __restrict__ wv, const float* __restrict__ wo) {
    int z = blockIdx.y;
    const float* src = (z == 0) ? wq : (z == 1) ? wk : (z == 2) ? wv : wo;
    int i = blockIdx.x * 256 + threadIdx.x;
    float v = src[i];
    __nv_bfloat16 h = __float2bfloat16(v);
    size_t o = (size_t)z * DDIM * DDIM + i;
    g_Wh[o] = h;
    g_Wl[o] = __float2bfloat16(v - __bfloat162float(h));
}

// ---------------- pipelined GEMM body: C = A W^T (+bias) -------------------
// stages at dsm: stage p occupies [p*4*TS, (p+1)*4*TS) elems: Ah,Al,Bh,Bl
__device__ __forceinline__ void gemm_pipe(
    char* dsm, u32 sb,
    const __nv_bfloat16* Ahp, const __nv_bfloat16* Alp,
    const __nv_bfloat16* Bhp, const __nv_bfloat16* Blp,
    int wm, int wn, int g, int tg, float acc[4][4][4])
{
    __nv_bfloat16* st = (__nv_bfloat16*)dsm;

    // prefetch chunk 0 into stage 0
    cp_tile128(sb, Ahp, DDIM);
    cp_tile128(sb + TS * 2, Alp, DDIM);
    cp_tile128(sb + 2 * TS * 2, Bhp, DDIM);
    cp_tile128(sb + 3 * TS * 2, Blp, DDIM);
    cp_commit();

    for (int ki = 0; ki < 16; ki++) {
        int p = ki & 1;
        if (ki + 1 < 16) {
            int np = (ki + 1) & 1;
            u32 nb = sb + (u32)np * 4 * TS * 2;
            int k0 = (ki + 1) * 32;
            cp_tile128(nb, Ahp + k0, DDIM);
            cp_tile128(nb + TS * 2, Alp + k0, DDIM);
            cp_tile128(nb + 2 * TS * 2, Bhp + k0, DDIM);
            cp_tile128(nb + 3 * TS * 2, Blp + k0, DDIM);
            cp_commit();
            cp_wait<1>();
        } else {
            cp_wait<0>();
        }
        __syncthreads();
        __nv_bfloat16* s = st + p * 4 * TS;
        mma_chunk<4>(s, s + TS, s + 2 * TS, s + 3 * TS, wm, wn, g, tg, acc);
        __syncthreads();
    }
}

// ---------------- QKV projections ------------------------------------------
__global__ __launch_bounds__(256) void qkv_mma(
    const float* __restrict__ bq, const float* __restrict__ bk,
    const float* __restrict__ bv)
{
    extern __shared__ __align__(16) char dsm[];
    u32 sb = (u32)__cvta_generic_to_shared(dsm);

    int tid = threadIdx.x, wid = tid >> 5, lane = tid & 31;
    int g = lane >> 2, tg = lane & 3;
    int wm = (wid & 1) * 64, wn = (wid >> 1) * 32;
    int z = blockIdx.z, e0 = blockIdx.x * 128, m0 = blockIdx.y * 128;
    const __nv_bfloat16* Wsh = g_Wh + (size_t)z * DDIM * DDIM + (size_t)e0 * DDIM;
    const __nv_bfloat16* Wsl = g_Wl + (size_t)z * DDIM * DDIM + (size_t)e0 * DDIM;
    const float* bias = (z == 0) ? bq : (z == 1) ? bk : bv;

    float acc[4][4][4];
#pragma unroll
    for (int a = 0; a < 4; a++)
#pragma unroll
        for (int b = 0; b < 4; b++)
#pragma unroll
            for (int c = 0; c < 4; c++) acc[a][b][c] = 0.f;

    gemm_pipe(dsm, sb, g_Xh + (size_t)m0 * DDIM, g_Xl + (size_t)m0 * DDIM,
              Wsh, Wsl, wm, wn, g, tg, acc);

    u32* stage = (u32*)dsm;
    float sc = (z == 0) ? 0.125f : 1.0f;
#pragma unroll
    for (int mf = 0; mf < 4; mf++)
#pragma unroll
        for (int nf = 0; nf < 4; nf++) {
            int r = wm + mf * 16 + g, c = wn + nf * 8 + tg * 2;
            float b0 = bias[e0 + c], b1 = bias[e0 + c + 1];
            u32 v00 = split_pack((acc[mf][nf][0] + b0) * sc);
            u32 v01 = split_pack((acc[mf][nf][1] + b1) * sc);
            u32 v10 = split_pack((acc[mf][nf][2] + b0) * sc);
            u32 v11 = split_pack((acc[mf][nf][3] + b1) * sc);
            if (z < 2) {
                stage[r * 132 + c] = v00;       stage[r * 132 + c + 1] = v01;
                stage[(r + 8) * 132 + c] = v10; stage[(r + 8) * 132 + c + 1] = v11;
            } else {  // transpose for V
                stage[c * 132 + r] = v00;       stage[(c + 1) * 132 + r] = v01;
                stage[c * 132 + r + 8] = v10;   stage[(c + 1) * 132 + r + 8] = v11;
            }
        }
    __syncthreads();

    int cp = tid & 63;
    if (z < 2) {
        __nv_bfloat16* oh = z ? g_Kh : g_Qh;
        __nv_bfloat16* ol = z ? g_Kl : g_Ql;
        for (int r0 = tid >> 6; r0 < 128; r0 += 4) {
            u32 ua = stage[r0 * 132 + cp * 2], ub = stage[r0 * 132 + cp * 2 + 1];
            u32 hw = (ua & 0xFFFFu) | (ub << 16);
            u32 lw = (ua >> 16) | (ub & 0xFFFF0000u);
            size_t o = (size_t)(m0 + r0) * DDIM + e0 + cp * 2;
            *(u32*)&oh[o] = hw;
            *(u32*)&ol[o] = lw;
        }
    } else {
        int bt = m0 >> 10, n0 = m0 & 1023;
        for (int d0 = tid >> 6; d0 < 128; d0 += 4) {
            u32 ua = stage[d0 * 132 + cp * 2], ub = stage[d0 * 132 + cp * 2 + 1];
            u32 hw = (ua & 0xFFFFu) | (ub << 16);
            u32 lw = (ua >> 16) | (ub & 0xFFFF0000u);
            size_t o = (size_t)(bt * 512 + e0 + d0) * NSEQ + n0 + cp * 2;
            *(u32*)&g_Vth[o] = hw;
            *(u32*)&g_Vtl[o] = lw;
        }
    }
}

// ---------------- fused flash attention ------------------------------------
// One CTA = 128 query rows of one (bt, head). 8 warps x 16 rows each.
// delta_c bias is constant along the softmax axis -> cancels, omitted.
#define KSTR 72
#define VSTR 136
#define FA_STAGE (128*KSTR*2 + 64*VSTR*2)            // elems per stage: 35840
#define FA_SMEM  (2 * FA_STAGE * 2)                   // 143360 bytes

__global__ __launch_bounds__(256) void fattn()
{
    extern __shared__ __align__(16) char dsm[];
    __nv_bfloat16* st = (__nv_bfloat16*)dsm;
    u32 sb = (u32)__cvta_generic_to_shared(dsm);

    int tid = threadIdx.x, wid = tid >> 5, lane = tid & 31;
    int g = lane >> 2, tg = lane & 3;
    int wm = wid * 16;
    int q0 = blockIdx.x * 128, inst = blockIdx.y;
    int bt = inst >> 3, h = inst & 7;

    const __nv_bfloat16* Qhp = g_Qh + (size_t)(bt * NSEQ + q0) * DDIM + h * DH;
    const __nv_bfloat16* Qlp = g_Ql + (size_t)(bt * NSEQ + q0) * DDIM + h * DH;
    const __nv_bfloat16* Khp = g_Kh + (size_t)(bt * NSEQ) * DDIM + h * DH;
    const __nv_bfloat16* Klp = g_Kl + (size_t)(bt * NSEQ) * DDIM + h * DH;
    const __nv_bfloat16* Vhp = g_Vth + (size_t)(bt * 512 + h * DH) * NSEQ;
    const __nv_bfloat16* Vlp = g_Vtl + (size_t)(bt * 512 + h * DH) * NSEQ;

    // ---- stage Q tile in stage-1 K area, extract fragments ----
    {
        __nv_bfloat16* Qs = st + FA_STAGE;   // stage1 Kh region
        int r = tid >> 1, c = (tid & 1) * 32;
#pragma unroll
        for (int p = 0; p < 4; p++) {
            *(uint4*)(Qs + r * KSTR + c + p * 8) = *(const uint4*)(Qhp + (size_t)r * DDIM + c + p * 8);
            *(uint4*)(Qs + 128 * KSTR + r * KSTR + c + p * 8) = *(const uint4*)(Qlp + (size_t)r * DDIM + c + p * 8);
        }
    }
    __syncthreads();
    u32 qh[4][4], ql[4][4];
    {
        __nv_bfloat16* Qs = st + FA_STAGE;
        __nv_bfloat16* Qs2 = Qs + 128 * KSTR;
#pragma unroll
        for (int kc = 0; kc < 4; kc++) {
            int k0 = kc * 16 + tg * 2;
            qh[kc][0] = *(const u32*)&Qs[(wm + g) * KSTR + k0];
            qh[kc][1] = *(const u32*)&Qs[(wm + g + 8) * KSTR + k0];
            qh[kc][2] = *(const u32*)&Qs[(wm + g) * KSTR + k0 + 8];
            qh[kc][3] = *(const u32*)&Qs[(wm + g + 8) * KSTR + k0 + 8];
            ql[kc][0] = *(const u32*)&Qs2[(wm + g) * KSTR + k0];
            ql[kc][1] = *(const u32*)&Qs2[(wm + g + 8) * KSTR + k0];
            ql[kc][2] = *(const u32*)&Qs2[(wm + g) * KSTR + k0 + 8];
            ql[kc][3] = *(const u32*)&Qs2[(wm + g + 8) * KSTR + k0 + 8];
        }
    }
    __syncthreads();

    // ---- prefetch helper (lambda-free) ----
    // K: 128x64 hi/lo, V: 64x128 hi/lo
#define FA_PREFETCH(pstage, jj)                                                   \
    {                                                                             \
        u32 b0 = sb + (u32)(pstage) * FA_STAGE * 2;                               \
        u32 bkh = b0, bkl = b0 + 128 * KSTR * 2;                                  \
        u32 bvh = b0 + 2 * 128 * KSTR * 2, bvl = bvh + 64 * VSTR * 2;             \
        for (int i = tid; i < 1024; i += 256) {                                   \
            int r = i >> 3, c = (i & 7) * 8;                                      \
            cp16(bkh + (u32)(r * KSTR + c) * 2, Khp + (size_t)((jj) + r) * DDIM + c); \
            cp16(bkl + (u32)(r * KSTR + c) * 2, Klp + (size_t)((jj) + r) * DDIM + c); \
        }                                                                         \
        for (int i = tid; i < 1024; i += 256) {                                   \
            int d = i >> 4, c = (i & 15) * 8;                                     \
            cp16(bvh + (u32)(d * VSTR + c) * 2, Vhp + (size_t)d * NSEQ + (jj) + c);   \
            cp16(bvl + (u32)(d * VSTR + c) * 2, Vlp + (size_t)d * NSEQ + (jj) + c);   \
        }                                                                         \
        cp_commit();                                                              \
    }

    FA_PREFETCH(0, 0);

    float mA = -1e30f, mB = -1e30f, lA = 0.f, lB = 0.f;
    float zacc[8][4];
#pragma unroll
    for (int n = 0; n < 8; n++)
#pragma unroll
        for (int c = 0; c < 4; c++) zacc[n][c] = 0.f;

    for (int t = 0; t < 8; t++) {
        int p = t & 1;
        if (t + 1 < 8) {
            FA_PREFETCH((t + 1) & 1, (t + 1) * 128);
            cp_wait<1>();
        } else {
            cp_wait<0>();
        }
        __syncthreads();

        __nv_bfloat16* Kh = st + p * FA_STAGE;
        __nv_bfloat16* Kl = Kh + 128 * KSTR;
        __nv_bfloat16* Vh = Kl + 128 * KSTR;
        __nv_bfloat16* Vl = Vh + 64 * VSTR;

        // ---- S = Q K^T ----
        float sacc[16][4];
#pragma unroll
        for (int n = 0; n < 16; n++)
#pragma unroll
            for (int c = 0; c < 4; c++) sacc[n][c] = 0.f;
#pragma unroll
        for (int kc = 0; kc < 4; kc++) {
            int k0 = kc * 16 + tg * 2;
#pragma unroll
            for (int nf = 0; nf < 16; nf++) {
                int n0 = nf * 8 + g;
                u32 bh[2], bl[2];
                bh[0] = *(const u32*)&Kh[n0 * KSTR + k0];
                bh[1] = *(const u32*)&Kh[n0 * KSTR + k0 + 8];
                bl[0] = *(const u32*)&Kl[n0 * KSTR + k0];
                bl[1] = *(const u32*)&Kl[n0 * KSTR + k0 + 8];
                mma_bf16(sacc[nf], qh[kc], bh);
                mma_bf16(sacc[nf], qh[kc], bl);
                mma_bf16(sacc[nf], ql[kc], bh);
            }
        }

        // ---- online softmax ----
        float nmA = mA, nmB = mB;
#pragma unroll
        for (int nf = 0; nf < 16; nf++) {
            nmA = fmaxf(nmA, fmaxf(sacc[nf][0], sacc[nf][1]));
            nmB = fmaxf(nmB, fmaxf(sacc[nf][2], sacc[nf][3]));
        }
#pragma unroll
        for (int o = 1; o <= 2; o <<= 1) {
            nmA = fmaxf(nmA, __shfl_xor_sync(0xFFFFFFFFu, nmA, o));
            nmB = fmaxf(nmB, __shfl_xor_sync(0xFFFFFFFFu, nmB, o));
        }
        float corrA = __expf(mA - nmA), corrB = __expf(mB - nmB);
        mA = nmA; mB = nmB;

        float sA = 0.f, sB = 0.f;
#pragma unroll
        for (int nf = 0; nf < 16; nf++) {
            sacc[nf][0] = __expf(sacc[nf][0] - nmA);
            sacc[nf][1] = __expf(sacc[nf][1] - nmA);
            sacc[nf][2] = __expf(sacc[nf][2] - nmB);
            sacc[nf][3] = __expf(sacc[nf][3] - nmB);
            sA += sacc[nf][0] + sacc[nf][1];
            sB += sacc[nf][2] + sacc[nf][3];
        }
#pragma unroll
        for (int o = 1; o <= 2; o <<= 1) {
            sA += __shfl_xor_sync(0xFFFFFFFFu, sA, o);
            sB += __shfl_xor_sync(0xFFFFFFFFu, sB, o);
        }
        lA = lA * corrA + sA;
        lB = lB * corrB + sB;

#pragma unroll
        for (int n = 0; n < 8; n++) {
            zacc[n][0] *= corrA; zacc[n][1] *= corrA;
            zacc[n][2] *= corrB; zacc[n][3] *= corrB;
        }

        // ---- Z += P V ----
#pragma unroll
        for (int kc2 = 0; kc2 < 8; kc2++) {
            u32 ah[4], al[4];
            split_pair(sacc[2*kc2][0],   sacc[2*kc2][1],   ah[0], al[0]);
            split_pair(sacc[2*kc2][2],   sacc[2*kc2][3],   ah[1], al[1]);
            split_pair(sacc[2*kc2+1][0], sacc[2*kc2+1][1], ah[2], al[2]);
            split_pair(sacc[2*kc2+1][2], sacc[2*kc2+1][3], ah[3], al[3]);
            int k0 = kc2 * 16 + tg * 2;
#pragma unroll
            for (int nf = 0; nf < 8; nf++) {
                int n0 = nf * 8 + g;
                u32 bh[2], bl[2];
                bh[0] = *(const u32*)&Vh[n0 * VSTR + k0];
                bh[1] = *(const u32*)&Vh[n0 * VSTR + k0 + 8];
                bl[0] = *(const u32*)&Vl[n0 * VSTR + k0];
                bl[1] = *(const u32*)&Vl[n0 * VSTR + k0 + 8];
                mma_bf16(zacc[nf], ah, bh);
                mma_bf16(zacc[nf], ah, bl);
                mma_bf16(zacc[nf], al, bh);
            }
        }
        __syncthreads();
    }

    // ---- epilogue ----
    float invA = 1.f / lA, invB = 1.f / lB;
    size_t rowA = (size_t)(bt * NSEQ + q0 + wm + g) * DDIM + h * DH;
    size_t rowB = rowA + 8 * DDIM;
#pragma unroll
    for (int nf = 0; nf < 8; nf++) {
        int c = nf * 8 + tg * 2;
        u32 hw, lw;
        split_pair(zacc[nf][0] * invA, zacc[nf][1] * invA, hw, lw);
        *(u32*)&g_Zh[rowA + c] = hw;
        *(u32*)&g_Zl[rowA + c] = lw;
        split_pair(zacc[nf][2] * invB, zacc[nf][3] * invB, hw, lw);
        *(u32*)&g_Zh[rowB + c] = hw;
        *(u32*)&g_Zl[rowB + c] = lw;
    }
}

// ---------------- out = Z Wo^T + bo ----------------------------------------
__global__ __launch_bounds__(256) void out_mma(const float* __restrict__ bo,
                                               float* __restrict__ out)
{
    extern __shared__ __align__(16) char dsm[];
    u32 sb = (u32)__cvta_generic_to_shared(dsm);

    int tid = threadIdx.x, wid = tid >> 5, lane = tid & 31;
    int g = lane >> 2, tg = lane & 3;
    int wm = (wid & 1) * 64, wn = (wid >> 1) * 32;
    int e0 = blockIdx.x * 128, m0 = blockIdx.y * 128;

    float acc[4][4][4];
#pragma unroll
    for (int a = 0; a < 4; a++)
#pragma unroll
        for (int b = 0; b < 4; b++)
#pragma unroll
            for (int c = 0; c < 4; c++) acc[a][b][c] = 0.f;

    gemm_pipe(dsm, sb, g_Zh + (size_t)m0 * DDIM, g_Zl + (size_t)m0 * DDIM,
              g_Wh + (size_t)3 * DDIM * DDIM + (size_t)e0 * DDIM,
              g_Wl + (size_t)3 * DDIM * DDIM + (size_t)e0 * DDIM,
              wm, wn, g, tg, acc);

    float* stage = (float*)dsm;
#pragma unroll
    for (int mf = 0; mf < 4; mf++)
#pragma unroll
        for (int nf = 0; nf < 4; nf++) {
            int r = wm + mf * 16 + g, c = wn + nf * 8 + tg * 2;
            float b0 = bo[e0 + c], b1 = bo[e0 + c + 1];
            stage[r * 132 + c]           = acc[mf][nf][0] + b0;
            stage[r * 132 + c + 1]       = acc[mf][nf][1] + b1;
            stage[(r + 8) * 132 + c]     = acc[mf][nf][2] + b0;
            stage[(r + 8) * 132 + c + 1] = acc[mf][nf][3] + b1;
        }
    __syncthreads();

    int cp = tid & 63;
    for (int r0 = tid >> 6; r0 < 128; r0 += 4) {
        float2 v = make_float2(stage[r0 * 132 + cp * 2], stage[r0 * 132 + cp * 2 + 1]);
        *(float2*)&out[(size_t)(m0 + r0) * DDIM + e0 + cp * 2] = v;
    }
}

// ---------------- launch ----------------------------------------------------
#define GEMM_SMEM (8 * TS * 2)   // 81920

extern "C" void kernel_launch(void* const* d_in, const int* in_sizes, int n_in,
                              void* d_out, int out_size)
{
    const float* X  = (const float*)d_in[0];
    const float* Wq = (const float*)d_in[1];
    const float* bq = (const float*)d_in[2];
    const float* Wk = (const float*)d_in[3];
    const float* bk = (const float*)d_in[4];
    const float* Wv = (const float*)d_in[5];
    const float* bv = (const float*)d_in[6];
    const float* Wo = (const float*)d_in[7];
    const float* bo = (const float*)d_in[8];
    float* out = (float*)d_out;

    cudaFuncSetAttribute(qkv_mma, cudaFuncAttributeMaxDynamicSharedMemorySize, GEMM_SMEM);
    cudaFuncSetAttribute(fattn,   cudaFuncAttributeMaxDynamicSharedMemorySize, FA_SMEM);
    cudaFuncSetAttribute(out_mma, cudaFuncAttributeMaxDynamicSharedMemorySize, GEMM_SMEM);

    int nX = MTOT * DDIM, nW = DDIM * DDIM;
    conv_x<<<(nX + 255) / 256, 256>>>(X, nX);
    conv_w<<<dim3(nW / 256, 4), 256>>>(Wq, Wk, Wv, Wo);

    qkv_mma<<<dim3(4, 128, 3), 256, GEMM_SMEM>>>(bq, bk, bv);
    fattn<<<dim3(NSEQ / 128, NINST), 256, FA_SMEM>>>();
    out_mma<<<dim3(4, 128), 256, GEMM_SMEM>>>(bo, out);
}

// round 8
// speedup vs baseline: 3.7799x; 1.0242x over previous
#include <cuda_runtime.h>
#include <cuda_bf16.h>
#include <stdint.h>

typedef uint32_t u32;
typedef unsigned short u16;

#define MTOT 16384   // B*T*N
#define DDIM 512
#define NSEQ 1024
#define DH 64
#define NINST 128    // (B*T)*HEADS

// ---------------- scratch (device globals; no allocation allowed) ----------
__device__ __nv_bfloat16 g_Xh[MTOT*DDIM], g_Xl[MTOT*DDIM];
__device__ __nv_bfloat16 g_Wh[4*DDIM*DDIM], g_Wl[4*DDIM*DDIM];
__device__ __nv_bfloat16 g_Qh[MTOT*DDIM], g_Ql[MTOT*DDIM];
__device__ __nv_bfloat16 g_Kh[MTOT*DDIM], g_Kl[MTOT*DDIM];
__device__ __nv_bfloat16 g_Vth[MTOT*DDIM], g_Vtl[MTOT*DDIM];  // V transposed [d, n]
__device__ __nv_bfloat16 g_Zh[MTOT*DDIM], g_Zl[MTOT*DDIM];

// ---------------- helpers ---------------------------------------------------
__device__ __forceinline__ void mma_bf16(float* c, const u32* a, const u32* b) {
    asm volatile(
        "mma.sync.aligned.m16n8k16.row.col.f32.bf16.bf16.f32 "
        "{%0,%1,%2,%3}, {%4,%5,%6,%7}, {%8,%9}, {%0,%1,%2,%3};"
        : "+f"(c[0]), "+f"(c[1]), "+f"(c[2]), "+f"(c[3])
        : "r"(a[0]), "r"(a[1]), "r"(a[2]), "r"(a[3]), "r"(b[0]), "r"(b[1]));
}

__device__ __forceinline__ void ldm_x4(u32& r0, u32& r1, u32& r2, u32& r3, u32 addr) {
    asm volatile("ldmatrix.sync.aligned.m8n8.x4.shared.b16 {%0,%1,%2,%3}, [%4];"
                 : "=r"(r0), "=r"(r1), "=r"(r2), "=r"(r3) : "r"(addr));
}
// per-lane byte offsets for A-type (16x16) / B-type (two 8x16) fragments
__device__ __forceinline__ u32 ldm_aoff(int lane, int str) {
    int m = lane >> 3, r = lane & 7;
    return (u32)((((m & 1) * 8 + r) * str + (m >> 1) * 8) * 2);
}
__device__ __forceinline__ u32 ldm_boff(int lane, int str) {
    int m = lane >> 3, r = lane & 7;
    return (u32)((((m >> 1) * 8 + r) * str + (m & 1) * 8) * 2);
}

__device__ __forceinline__ void cp16(u32 dst, const void* src) {
    asm volatile("cp.async.cg.shared.global [%0], [%1], 16;" :: "r"(dst), "l"(src));
}
__device__ __forceinline__ void cp_commit() {
    asm volatile("cp.async.commit_group;" ::: "memory");
}
template<int N>
__device__ __forceinline__ void cp_wait() {
    asm volatile("cp.async.wait_group %0;" :: "n"(N) : "memory");
}

__device__ __forceinline__ u32 split_pack(float v) {
    __nv_bfloat16 h = __float2bfloat16(v);
    float r = v - __bfloat162float(h);
    __nv_bfloat16 l = __float2bfloat16(r);
    return (u32)__bfloat16_as_ushort(h) | ((u32)__bfloat16_as_ushort(l) << 16);
}
__device__ __forceinline__ void split_pair(float x0, float x1, u32& hw, u32& lw) {
    __nv_bfloat162 h = __floats2bfloat162_rn(x0, x1);
    float r0 = x0 - __bfloat162float(h.x);
    float r1 = x1 - __bfloat162float(h.y);
    __nv_bfloat162 l = __floats2bfloat162_rn(r0, r1);
    hw = *(u32*)&h;
    lw = *(u32*)&l;
}

#define TS 5120   // 128*40 elems per GEMM tile

// async-copy a 128x32 bf16 tile (row stride ld) into smem (stride 40)
__device__ __forceinline__ void cp_tile128(u32 dst, const __nv_bfloat16* src, int ld) {
    int t = threadIdx.x;
#pragma unroll
    for (int i = t; i < 512; i += 256) {
        int r = i >> 2, c = (i & 3) * 8;
        cp16(dst + (u32)(r * 40 + c) * 2, src + (size_t)r * ld + c);
    }
}

// one K=32 chunk of 3-pass bf16 mma via ldmatrix. Warp tile 64x32.
// base = stage byte addr (Ah at +0, Al +TS*2, Bh +2*TS*2, Bl +3*TS*2)
__device__ __forceinline__ void mma_chunk4(u32 base, int wm, int wn,
                                           u32 aoff, u32 boff, float acc[4][4][4])
{
    u32 A0 = base + (u32)wm * 80 + aoff;
    u32 L0 = A0 + TS * 2;
    u32 B0 = base + 2 * TS * 2 + (u32)wn * 80 + boff;
    u32 M0 = B0 + TS * 2;
#pragma unroll
    for (int s = 0; s < 2; s++) {
        u32 ah[4][4], al[4][4];
#pragma unroll
        for (int mf = 0; mf < 4; mf++) {
            ldm_x4(ah[mf][0], ah[mf][1], ah[mf][2], ah[mf][3], A0 + mf * (16 * 80) + s * 32);
            ldm_x4(al[mf][0], al[mf][1], al[mf][2], al[mf][3], L0 + mf * (16 * 80) + s * 32);
        }
        u32 bh[4][2], bl[4][2];
#pragma unroll
        for (int np = 0; np < 2; np++) {
            ldm_x4(bh[2*np][0], bh[2*np][1], bh[2*np+1][0], bh[2*np+1][1],
                   B0 + np * (16 * 80) + s * 32);
            ldm_x4(bl[2*np][0], bl[2*np][1], bl[2*np+1][0], bl[2*np+1][1],
                   M0 + np * (16 * 80) + s * 32);
        }
#pragma unroll
        for (int mf = 0; mf < 4; mf++)
#pragma unroll
            for (int nf = 0; nf < 4; nf++) {
                mma_bf16(acc[mf][nf], ah[mf], bh[nf]);
                mma_bf16(acc[mf][nf], ah[mf], bl[nf]);
                mma_bf16(acc[mf][nf], al[mf], bh[nf]);
            }
    }
}

// ---------------- conversion: fp32 -> bf16 hi/lo ----------------------------
__global__ void conv_x(const float* __restrict__ src, int n) {
    int i = blockIdx.x * 256 + threadIdx.x;
    if (i < n) {
        float v = src[i];
        __nv_bfloat16 h = __float2bfloat16(v);
        g_Xh[i] = h;
        g_Xl[i] = __float2bfloat16(v - __bfloat162float(h));
    }
}
__global__ void conv_w(const float* __restrict__ wq, const float* __restrict__ wk,
                       const float* __restrict__ wv, const float* __restrict__ wo) {
    int z = blockIdx.y;
    const float* src = (z == 0) ? wq : (z == 1) ? wk : (z == 2) ? wv : wo;
    int i = blockIdx.x * 256 + threadIdx.x;
    float v = src[i];
    __nv_bfloat16 h = __float2bfloat16(v);
    size_t o = (size_t)z * DDIM * DDIM + i;
    g_Wh[o] = h;
    g_Wl[o] = __float2bfloat16(v - __bfloat162float(h));
}

// ---------------- pipelined GEMM body --------------------------------------
__device__ __forceinline__ void gemm_pipe(
    u32 sb,
    const __nv_bfloat16* Ahp, const __nv_bfloat16* Alp,
    const __nv_bfloat16* Bhp, const __nv_bfloat16* Blp,
    int wm, int wn, u32 aoff, u32 boff, float acc[4][4][4])
{
    cp_tile128(sb, Ahp, DDIM);
    cp_tile128(sb + TS * 2, Alp, DDIM);
    cp_tile128(sb + 2 * TS * 2, Bhp, DDIM);
    cp_tile128(sb + 3 * TS * 2, Blp, DDIM);
    cp_commit();

    for (int ki = 0; ki < 16; ki++) {
        int p = ki & 1;
        if (ki + 1 < 16) {
            u32 nb = sb + (u32)((ki + 1) & 1) * 4 * TS * 2;
            int k0 = (ki + 1) * 32;
            cp_tile128(nb, Ahp + k0, DDIM);
            cp_tile128(nb + TS * 2, Alp + k0, DDIM);
            cp_tile128(nb + 2 * TS * 2, Bhp + k0, DDIM);
            cp_tile128(nb + 3 * TS * 2, Blp + k0, DDIM);
            cp_commit();
            cp_wait<1>();
        } else {
            cp_wait<0>();
        }
        __syncthreads();
        mma_chunk4(sb + (u32)p * 4 * TS * 2, wm, wn, aoff, boff, acc);
        __syncthreads();
    }
}

// ---------------- QKV projections ------------------------------------------
__global__ __launch_bounds__(256) void qkv_mma(
    const float* __restrict__ bq, const float* __restrict__ bk,
    const float* __restrict__ bv)
{
    extern __shared__ __align__(16) char dsm[];
    u32 sb = (u32)__cvta_generic_to_shared(dsm);

    int tid = threadIdx.x, wid = tid >> 5, lane = tid & 31;
    int g = lane >> 2, tg = lane & 3;
    int wm = (wid & 1) * 64, wn = (wid >> 1) * 32;
    u32 aoff = ldm_aoff(lane, 40), boff = ldm_boff(lane, 40);
    int z = blockIdx.z, e0 = blockIdx.x * 128, m0 = blockIdx.y * 128;
    const __nv_bfloat16* Wsh = g_Wh + (size_t)z * DDIM * DDIM + (size_t)e0 * DDIM;
    const __nv_bfloat16* Wsl = g_Wl + (size_t)z * DDIM * DDIM + (size_t)e0 * DDIM;
    const float* bias = (z == 0) ? bq : (z == 1) ? bk : bv;

    float acc[4][4][4];
#pragma unroll
    for (int a = 0; a < 4; a++)
#pragma unroll
        for (int b = 0; b < 4; b++)
#pragma unroll
            for (int c = 0; c < 4; c++) acc[a][b][c] = 0.f;

    gemm_pipe(sb, g_Xh + (size_t)m0 * DDIM, g_Xl + (size_t)m0 * DDIM,
              Wsh, Wsl, wm, wn, aoff, boff, acc);

    u32* stage = (u32*)dsm;
    float sc = (z == 0) ? 0.125f : 1.0f;
#pragma unroll
    for (int mf = 0; mf < 4; mf++)
#pragma unroll
        for (int nf = 0; nf < 4; nf++) {
            int r = wm + mf * 16 + g, c = wn + nf * 8 + tg * 2;
            float b0 = bias[e0 + c], b1 = bias[e0 + c + 1];
            u32 v00 = split_pack((acc[mf][nf][0] + b0) * sc);
            u32 v01 = split_pack((acc[mf][nf][1] + b1) * sc);
            u32 v10 = split_pack((acc[mf][nf][2] + b0) * sc);
            u32 v11 = split_pack((acc[mf][nf][3] + b1) * sc);
            if (z < 2) {
                stage[r * 132 + c] = v00;       stage[r * 132 + c + 1] = v01;
                stage[(r + 8) * 132 + c] = v10; stage[(r + 8) * 132 + c + 1] = v11;
            } else {  // transpose for V
                stage[c * 132 + r] = v00;       stage[(c + 1) * 132 + r] = v01;
                stage[c * 132 + r + 8] = v10;   stage[(c + 1) * 132 + r + 8] = v11;
            }
        }
    __syncthreads();

    int cp = tid & 63;
    if (z < 2) {
        __nv_bfloat16* oh = z ? g_Kh : g_Qh;
        __nv_bfloat16* ol = z ? g_Kl : g_Ql;
        for (int r0 = tid >> 6; r0 < 128; r0 += 4) {
            u32 ua = stage[r0 * 132 + cp * 2], ub = stage[r0 * 132 + cp * 2 + 1];
            u32 hw = (ua & 0xFFFFu) | (ub << 16);
            u32 lw = (ua >> 16) | (ub & 0xFFFF0000u);
            size_t o = (size_t)(m0 + r0) * DDIM + e0 + cp * 2;
            *(u32*)&oh[o] = hw;
            *(u32*)&ol[o] = lw;
        }
    } else {
        int bt = m0 >> 10, n0 = m0 & 1023;
        for (int d0 = tid >> 6; d0 < 128; d0 += 4) {
            u32 ua = stage[d0 * 132 + cp * 2], ub = stage[d0 * 132 + cp * 2 + 1];
            u32 hw = (ua & 0xFFFFu) | (ub << 16);
            u32 lw = (ua >> 16) | (ub & 0xFFFF0000u);
            size_t o = (size_t)(bt * 512 + e0 + d0) * NSEQ + n0 + cp * 2;
            *(u32*)&g_Vth[o] = hw;
            *(u32*)&g_Vtl[o] = lw;
        }
    }
}

// ---------------- fused flash attention ------------------------------------
// One CTA = 128 query rows of one (bt, head), 8 warps x 16 rows.
// KV tiles of 64 keys, double-buffered -> 72KB smem -> 2 CTAs/SM.
// delta_c bias is constant along the softmax axis -> cancels, omitted.
#define KSTR 72
#define FA_STAGE (4 * 64 * KSTR)          // elems per stage: Kh,Kl,Vh,Vl
#define FA_SMEM  (2 * FA_STAGE * 2)       // 73728 bytes

__global__ __launch_bounds__(256, 2) void fattn()
{
    extern __shared__ __align__(16) char dsm[];
    __nv_bfloat16* st = (__nv_bfloat16*)dsm;
    u32 sb = (u32)__cvta_generic_to_shared(dsm);

    int tid = threadIdx.x, wid = tid >> 5, lane = tid & 31;
    int g = lane >> 2, tg = lane & 3;
    int wm = wid * 16;
    int q0 = blockIdx.x * 128, inst = blockIdx.y;
    int bt = inst >> 3, h = inst & 7;

    const __nv_bfloat16* Qhp = g_Qh + (size_t)(bt * NSEQ + q0) * DDIM + h * DH;
    const __nv_bfloat16* Qlp = g_Ql + (size_t)(bt * NSEQ + q0) * DDIM + h * DH;
    const __nv_bfloat16* Khp = g_Kh + (size_t)(bt * NSEQ) * DDIM + h * DH;
    const __nv_bfloat16* Klp = g_Kl + (size_t)(bt * NSEQ) * DDIM + h * DH;
    const __nv_bfloat16* Vhp = g_Vth + (size_t)(bt * 512 + h * DH) * NSEQ;
    const __nv_bfloat16* Vlp = g_Vtl + (size_t)(bt * 512 + h * DH) * NSEQ;

    u32 aoffK = ldm_aoff(lane, KSTR);
    u32 boffK = ldm_boff(lane, KSTR);

    // ---- stage Q (128x64 hi/lo) in stage-1 area, extract fragments ----
    {
        __nv_bfloat16* Qs = st + FA_STAGE;            // Qh 128*72
        __nv_bfloat16* Qs2 = Qs + 128 * KSTR;         // Ql 128*72
        int r = tid >> 1, c = (tid & 1) * 32;
#pragma unroll
        for (int p = 0; p < 4; p++) {
            *(uint4*)(Qs + r * KSTR + c + p * 8) = *(const uint4*)(Qhp + (size_t)r * DDIM + c + p * 8);
            *(uint4*)(Qs2 + r * KSTR + c + p * 8) = *(const uint4*)(Qlp + (size_t)r * DDIM + c + p * 8);
        }
    }
    __syncthreads();
    u32 qh[4][4], ql[4][4];
    {
        u32 Qb = sb + FA_STAGE * 2 + (u32)wm * KSTR * 2 + aoffK;
        u32 Qb2 = Qb + 128 * KSTR * 2;
#pragma unroll
        for (int kc = 0; kc < 4; kc++) {
            ldm_x4(qh[kc][0], qh[kc][1], qh[kc][2], qh[kc][3], Qb + kc * 32);
            ldm_x4(ql[kc][0], ql[kc][1], ql[kc][2], ql[kc][3], Qb2 + kc * 32);
        }
    }
    __syncthreads();

    // prefetch a 64-key stage: K 64x64 hi/lo + V 64x64 hi/lo
#define FA_PREFETCH(pstage, jj)                                                   \
    {                                                                             \
        u32 b0 = sb + (u32)(pstage) * FA_STAGE * 2;                               \
        u32 bkl = b0 + 64 * KSTR * 2;                                             \
        u32 bvh = b0 + 2 * 64 * KSTR * 2;                                         \
        u32 bvl = b0 + 3 * 64 * KSTR * 2;                                         \
        for (int i = tid; i < 512; i += 256) {                                    \
            int r = i >> 3, c = (i & 7) * 8;                                      \
            u32 so = (u32)(r * KSTR + c) * 2;                                     \
            cp16(b0 + so,  Khp + (size_t)((jj) + r) * DDIM + c);                  \
            cp16(bkl + so, Klp + (size_t)((jj) + r) * DDIM + c);                  \
            cp16(bvh + so, Vhp + (size_t)r * NSEQ + (jj) + c);                    \
            cp16(bvl + so, Vlp + (size_t)r * NSEQ + (jj) + c);                    \
        }                                                                         \
        cp_commit();                                                              \
    }

    FA_PREFETCH(0, 0);

    float mA = -1e30f, mB = -1e30f, lA = 0.f, lB = 0.f;
    float zacc[8][4];
#pragma unroll
    for (int n = 0; n < 8; n++)
#pragma unroll
        for (int c = 0; c < 4; c++) zacc[n][c] = 0.f;

    for (int t = 0; t < 16; t++) {
        int p = t & 1;
        if (t + 1 < 16) {
            FA_PREFETCH((t + 1) & 1, (t + 1) * 64);
            cp_wait<1>();
        } else {
            cp_wait<0>();
        }
        __syncthreads();

        u32 Kb = sb + (u32)p * FA_STAGE * 2 + boffK;
        u32 Kb2 = Kb + 64 * KSTR * 2;
        u32 Vb = sb + (u32)p * FA_STAGE * 2 + 2 * 64 * KSTR * 2 + boffK;
        u32 Vb2 = Vb + 64 * KSTR * 2;

        // ---- S = Q K^T (64 keys -> 8 n-frags) ----
        float sacc[8][4];
#pragma unroll
        for (int n = 0; n < 8; n++)
#pragma unroll
            for (int c = 0; c < 4; c++) sacc[n][c] = 0.f;
#pragma unroll
        for (int kc = 0; kc < 4; kc++) {
#pragma unroll
            for (int np = 0; np < 4; np++) {
                u32 h0, h1, h2, h3, l0, l1, l2, l3;
                ldm_x4(h0, h1, h2, h3, Kb + np * (16 * KSTR * 2) + kc * 32);
                ldm_x4(l0, l1, l2, l3, Kb2 + np * (16 * KSTR * 2) + kc * 32);
                u32 bA[2] = {h0, h1}, bB[2] = {h2, h3};
                u32 cA[2] = {l0, l1}, cB[2] = {l2, l3};
                mma_bf16(sacc[2*np],     qh[kc], bA);
                mma_bf16(sacc[2*np],     qh[kc], cA);
                mma_bf16(sacc[2*np],     ql[kc], bA);
                mma_bf16(sacc[2*np+1],   qh[kc], bB);
                mma_bf16(sacc[2*np+1],   qh[kc], cB);
                mma_bf16(sacc[2*np+1],   ql[kc], bB);
            }
        }

        // ---- online softmax ----
        float nmA = mA, nmB = mB;
#pragma unroll
        for (int nf = 0; nf < 8; nf++) {
            nmA = fmaxf(nmA, fmaxf(sacc[nf][0], sacc[nf][1]));
            nmB = fmaxf(nmB, fmaxf(sacc[nf][2], sacc[nf][3]));
        }
#pragma unroll
        for (int o = 1; o <= 2; o <<= 1) {
            nmA = fmaxf(nmA, __shfl_xor_sync(0xFFFFFFFFu, nmA, o));
            nmB = fmaxf(nmB, __shfl_xor_sync(0xFFFFFFFFu, nmB, o));
        }
        float corrA = __expf(mA - nmA), corrB = __expf(mB - nmB);
        mA = nmA; mB = nmB;

        float sA = 0.f, sB = 0.f;
#pragma unroll
        for (int nf = 0; nf < 8; nf++) {
            sacc[nf][0] = __expf(sacc[nf][0] - nmA);
            sacc[nf][1] = __expf(sacc[nf][1] - nmA);
            sacc[nf][2] = __expf(sacc[nf][2] - nmB);
            sacc[nf][3] = __expf(sacc[nf][3] - nmB);
            sA += sacc[nf][0] + sacc[nf][1];
            sB += sacc[nf][2] + sacc[nf][3];
        }
#pragma unroll
        for (int o = 1; o <= 2; o <<= 1) {
            sA += __shfl_xor_sync(0xFFFFFFFFu, sA, o);
            sB += __shfl_xor_sync(0xFFFFFFFFu, sB, o);
        }
        lA = lA * corrA + sA;
        lB = lB * corrB + sB;

#pragma unroll
        for (int n = 0; n < 8; n++) {
            zacc[n][0] *= corrA; zacc[n][1] *= corrA;
            zacc[n][2] *= corrB; zacc[n][3] *= corrB;
        }

        // ---- Z += P V (4 key-chunks of 16) ----
#pragma unroll
        for (int kc2 = 0; kc2 < 4; kc2++) {
            u32 ah[4], al[4];
            split_pair(sacc[2*kc2][0],   sacc[2*kc2][1],   ah[0], al[0]);
            split_pair(sacc[2*kc2][2],   sacc[2*kc2][3],   ah[1], al[1]);
            split_pair(sacc[2*kc2+1][0], sacc[2*kc2+1][1], ah[2], al[2]);
            split_pair(sacc[2*kc2+1][2], sacc[2*kc2+1][3], ah[3], al[3]);
#pragma unroll
            for (int np = 0; np < 4; np++) {
                u32 h0, h1, h2, h3, l0, l1, l2, l3;
                ldm_x4(h0, h1, h2, h3, Vb + np * (16 * KSTR * 2) + kc2 * 32);
                ldm_x4(l0, l1, l2, l3, Vb2 + np * (16 * KSTR * 2) + kc2 * 32);
                u32 bA[2] = {h0, h1}, bB[2] = {h2, h3};
                u32 cA[2] = {l0, l1}, cB[2] = {l2, l3};
                mma_bf16(zacc[2*np],   ah, bA);
                mma_bf16(zacc[2*np],   ah, cA);
                mma_bf16(zacc[2*np],   al, bA);
                mma_bf16(zacc[2*np+1], ah, bB);
                mma_bf16(zacc[2*np+1], ah, cB);
                mma_bf16(zacc[2*np+1], al, bB);
            }
        }
        __syncthreads();
    }

    // ---- epilogue ----
    float invA = 1.f / lA, invB = 1.f / lB;
    size_t rowA = (size_t)(bt * NSEQ + q0 + wm + g) * DDIM + h * DH;
    size_t rowB = rowA + 8 * DDIM;
#pragma unroll
    for (int nf = 0; nf < 8; nf++) {
        int c = nf * 8 + tg * 2;
        u32 hw, lw;
        split_pair(zacc[nf][0] * invA, zacc[nf][1] * invA, hw, lw);
        *(u32*)&g_Zh[rowA + c] = hw;
        *(u32*)&g_Zl[rowA + c] = lw;
        split_pair(zacc[nf][2] * invB, zacc[nf][3] * invB, hw, lw);
        *(u32*)&g_Zh[rowB + c] = hw;
        *(u32*)&g_Zl[rowB + c] = lw;
    }
}

// ---------------- out = Z Wo^T + bo ----------------------------------------
__global__ __launch_bounds__(256) void out_mma(const float* __restrict__ bo,
                                               float* __restrict__ out)
{
    extern __shared__ __align__(16) char dsm[];
    u32 sb = (u32)__cvta_generic_to_shared(dsm);

    int tid = threadIdx.x, wid = tid >> 5, lane = tid & 31;
    int g = lane >> 2, tg = lane & 3;
    int wm = (wid & 1) * 64, wn = (wid >> 1) * 32;
    u32 aoff = ldm_aoff(lane, 40), boff = ldm_boff(lane, 40);
    int e0 = blockIdx.x * 128, m0 = blockIdx.y * 128;

    float acc[4][4][4];
#pragma unroll
    for (int a = 0; a < 4; a++)
#pragma unroll
        for (int b = 0; b < 4; b++)
#pragma unroll
            for (int c = 0; c < 4; c++) acc[a][b][c] = 0.f;

    gemm_pipe(sb, g_Zh + (size_t)m0 * DDIM, g_Zl + (size_t)m0 * DDIM,
              g_Wh + (size_t)3 * DDIM * DDIM + (size_t)e0 * DDIM,
              g_Wl + (size_t)3 * DDIM * DDIM + (size_t)e0 * DDIM,
              wm, wn, aoff, boff, acc);

    float* stage = (float*)dsm;
#pragma unroll
    for (int mf = 0; mf < 4; mf++)
#pragma unroll
        for (int nf = 0; nf < 4; nf++) {
            int r = wm + mf * 16 + g, c = wn + nf * 8 + tg * 2;
            float b0 = bo[e0 + c], b1 = bo[e0 + c + 1];
            stage[r * 132 + c]           = acc[mf][nf][0] + b0;
            stage[r * 132 + c + 1]       = acc[mf][nf][1] + b1;
            stage[(r + 8) * 132 + c]     = acc[mf][nf][2] + b0;
            stage[(r + 8) * 132 + c + 1] = acc[mf][nf][3] + b1;
        }
    __syncthreads();

    int cp = tid & 63;
    for (int r0 = tid >> 6; r0 < 128; r0 += 4) {
        float2 v = make_float2(stage[r0 * 132 + cp * 2], stage[r0 * 132 + cp * 2 + 1]);
        *(float2*)&out[(size_t)(m0 + r0) * DDIM + e0 + cp * 2] = v;
    }
}

// ---------------- launch ----------------------------------------------------
#define GEMM_SMEM (8 * TS * 2)   // 81920

extern "C" void kernel_launch(void* const* d_in, const int* in_sizes, int n_in,
                              void* d_out, int out_size)
{
    const float* X  = (const float*)d_in[0];
    const float* Wq = (const float*)d_in[1];
    const float* bq = (const float*)d_in[2];
    const float* Wk = (const float*)d_in[3];
    const float* bk = (const float*)d_in[4];
    const float* Wv = (const float*)d_in[5];
    const float* bv = (const float*)d_in[6];
    const float* Wo = (const float*)d_in[7];
    const float* bo = (const float*)d_in[8];
    float* out = (float*)d_out;

    cudaFuncSetAttribute(qkv_mma, cudaFuncAttributeMaxDynamicSharedMemorySize, GEMM_SMEM);
    cudaFuncSetAttribute(fattn,   cudaFuncAttributeMaxDynamicSharedMemorySize, FA_SMEM);
    cudaFuncSetAttribute(out_mma, cudaFuncAttributeMaxDynamicSharedMemorySize, GEMM_SMEM);

    int nX = MTOT * DDIM, nW = DDIM * DDIM;
    conv_x<<<(nX + 255) / 256, 256>>>(X, nX);
    conv_w<<<dim3(nW / 256, 4), 256>>>(Wq, Wk, Wv, Wo);

    qkv_mma<<<dim3(4, 128, 3), 256, GEMM_SMEM>>>(bq, bk, bv);
    fattn<<<dim3(NSEQ / 128, NINST), 256, FA_SMEM>>>();
    out_mma<<<dim3(4, 128), 256, GEMM_SMEM>>>(bo, out);
}